// round 1
// baseline (speedup 1.0000x reference)
#include <cuda_runtime.h>
#include <math.h>

// Problem constants (fixed by the reference)
#define B_  4
#define T_  2048
#define D_  1024
#define H_  16
#define DH_ 64
#define M_  (B_ * T_)   // 8192 rows

// Scratch (device globals — no allocation allowed in kernel_launch)
__device__ float g_Q[(size_t)M_ * D_];
__device__ float g_K[(size_t)M_ * D_];
__device__ float g_V[(size_t)M_ * D_];
__device__ float g_A[(size_t)M_ * D_];

// ---------------------------------------------------------------------------
// GEMM: C[M,N] = A[M,K] @ W[K,N] + bias[N]
// 64x64 tile, BK=16, 256 threads, 4x4 register blocking per thread.
// ---------------------------------------------------------------------------
__global__ __launch_bounds__(256) void gemm_bias(
    const float* __restrict__ A, const float* __restrict__ W,
    const float* __restrict__ bias, float* __restrict__ C,
    int M, int N, int K)
{
    __shared__ float Asm[16][68];  // [kk][row]  (transposed for float4 reads)
    __shared__ float Bsm[16][68];  // [kk][col]

    const int tx = threadIdx.x % 16;
    const int ty = threadIdx.x / 16;
    const int row0 = blockIdx.y * 64;
    const int col0 = blockIdx.x * 64;

    float acc[4][4] = {};

    for (int k0 = 0; k0 < K; k0 += 16) {
        // Load A tile (64 rows x 16 k), store transposed.
        {
            const int kk = threadIdx.x % 16;
            const int r0 = threadIdx.x / 16;
#pragma unroll
            for (int rr = 0; rr < 4; rr++) {
                const int row = r0 + rr * 16;
                Asm[kk][row] = A[(size_t)(row0 + row) * K + k0 + kk];
            }
        }
        // Load W tile (16 k x 64 cols), coalesced.
        {
            const int c   = threadIdx.x % 64;
            const int kk0 = threadIdx.x / 64;  // 0..3
#pragma unroll
            for (int kk = kk0; kk < 16; kk += 4)
                Bsm[kk][c] = W[(size_t)(k0 + kk) * N + col0 + c];
        }
        __syncthreads();

#pragma unroll
        for (int kk = 0; kk < 16; kk++) {
            const float4 a4 = *(const float4*)&Asm[kk][ty * 4];
            const float4 b4 = *(const float4*)&Bsm[kk][tx * 4];
            const float a[4] = {a4.x, a4.y, a4.z, a4.w};
            const float b[4] = {b4.x, b4.y, b4.z, b4.w};
#pragma unroll
            for (int i = 0; i < 4; i++)
#pragma unroll
                for (int j = 0; j < 4; j++)
                    acc[i][j] += a[i] * b[j];
        }
        __syncthreads();
    }

#pragma unroll
    for (int i = 0; i < 4; i++) {
        const int row = row0 + ty * 4 + i;
        float4 r;
        r.x = acc[i][0] + bias[col0 + tx * 4 + 0];
        r.y = acc[i][1] + bias[col0 + tx * 4 + 1];
        r.z = acc[i][2] + bias[col0 + tx * 4 + 2];
        r.w = acc[i][3] + bias[col0 + tx * 4 + 3];
        *(float4*)&C[(size_t)row * N + col0 + tx * 4] = r;
    }
}

// ---------------------------------------------------------------------------
// Flash attention (fp32, online softmax).
// Block = (q-tile of 64 rows) x (one head) x (one batch). 256 threads.
// Loops over 32 k-tiles of 64. Per-thread 4x4 register blocks for S and O.
// ---------------------------------------------------------------------------
#define SROW 68   // padded row stride (floats), keeps 16B alignment
#define ATTN_SMEM_FLOATS (4 * 64 * SROW + 3 * 64)

__global__ __launch_bounds__(256) void attn_kernel(
    const float* __restrict__ Qg, const float* __restrict__ Kg,
    const float* __restrict__ Vg, float* __restrict__ Og)
{
    extern __shared__ float sm[];
    float* Qs  = sm;                 // [64][SROW]
    float* Ks  = Qs + 64 * SROW;
    float* Vs  = Ks + 64 * SROW;
    float* Ss  = Vs + 64 * SROW;
    float* m_s = Ss + 64 * SROW;     // [64]
    float* l_s = m_s + 64;
    float* c_s = l_s + 64;

    const int tid = threadIdx.x;
    const int tx = tid % 16;
    const int ty = tid / 16;
    const int q0 = blockIdx.x * 64;
    const int h  = blockIdx.y;
    const int b  = blockIdx.z;
    const size_t base = (size_t)b * T_ * D_ + (size_t)h * DH_;

    // Load Q tile (64 x 64) as float4
    {
        const int d  = (tid % 16) * 4;
        const int r0 = tid / 16;
#pragma unroll
        for (int rr = 0; rr < 4; rr++) {
            const int row = r0 + rr * 16;
            *(float4*)&Qs[row * SROW + d] =
                *(const float4*)&Qg[base + (size_t)(q0 + row) * D_ + d];
        }
    }
    if (tid < 64) { m_s[tid] = -1e30f; l_s[tid] = 0.0f; }

    float o[4][4] = {};
    __syncthreads();

    for (int s0 = 0; s0 < T_; s0 += 64) {
        // Load K, V tiles
        {
            const int d  = (tid % 16) * 4;
            const int r0 = tid / 16;
#pragma unroll
            for (int rr = 0; rr < 4; rr++) {
                const int row = r0 + rr * 16;
                *(float4*)&Ks[row * SROW + d] =
                    *(const float4*)&Kg[base + (size_t)(s0 + row) * D_ + d];
                *(float4*)&Vs[row * SROW + d] =
                    *(const float4*)&Vg[base + (size_t)(s0 + row) * D_ + d];
            }
        }
        __syncthreads();

        // S = (Q K^T) * scale  — 4x4 per thread over dh=64
        float s[4][4] = {};
#pragma unroll
        for (int d4 = 0; d4 < 16; d4++) {
            float4 q4[4], k4[4];
#pragma unroll
            for (int i = 0; i < 4; i++)
                q4[i] = *(const float4*)&Qs[(ty * 4 + i) * SROW + d4 * 4];
#pragma unroll
            for (int j = 0; j < 4; j++)
                k4[j] = *(const float4*)&Ks[(tx * 4 + j) * SROW + d4 * 4];
#pragma unroll
            for (int i = 0; i < 4; i++)
#pragma unroll
                for (int j = 0; j < 4; j++)
                    s[i][j] += q4[i].x * k4[j].x + q4[i].y * k4[j].y +
                               q4[i].z * k4[j].z + q4[i].w * k4[j].w;
        }
#pragma unroll
        for (int i = 0; i < 4; i++)
#pragma unroll
            for (int j = 0; j < 4; j++)
                Ss[(ty * 4 + i) * SROW + tx * 4 + j] = s[i][j] * 0.125f;
        __syncthreads();

        // Online softmax, one thread per row
        if (tid < 64) {
            const float mo = m_s[tid];
            float mn = mo;
#pragma unroll 8
            for (int c = 0; c < 64; c++) mn = fmaxf(mn, Ss[tid * SROW + c]);
            const float corr = __expf(mo - mn);
            float l = l_s[tid] * corr;
#pragma unroll 8
            for (int c = 0; c < 64; c++) {
                const float p = __expf(Ss[tid * SROW + c] - mn);
                Ss[tid * SROW + c] = p;
                l += p;
            }
            m_s[tid] = mn; l_s[tid] = l; c_s[tid] = corr;
        }
        __syncthreads();

        // O = O*corr + P @ V
        float corr_r[4];
#pragma unroll
        for (int i = 0; i < 4; i++) corr_r[i] = c_s[ty * 4 + i];
#pragma unroll
        for (int i = 0; i < 4; i++)
#pragma unroll
            for (int j = 0; j < 4; j++)
                o[i][j] *= corr_r[i];

#pragma unroll
        for (int s4 = 0; s4 < 16; s4++) {
            float p[4][4];
#pragma unroll
            for (int i = 0; i < 4; i++) {
                const float4 p4 = *(const float4*)&Ss[(ty * 4 + i) * SROW + s4 * 4];
                p[i][0] = p4.x; p[i][1] = p4.y; p[i][2] = p4.z; p[i][3] = p4.w;
            }
#pragma unroll
            for (int u = 0; u < 4; u++) {
                const float4 v4 = *(const float4*)&Vs[(s4 * 4 + u) * SROW + tx * 4];
#pragma unroll
                for (int i = 0; i < 4; i++) {
                    o[i][0] += p[i][u] * v4.x;
                    o[i][1] += p[i][u] * v4.y;
                    o[i][2] += p[i][u] * v4.z;
                    o[i][3] += p[i][u] * v4.w;
                }
            }
        }
        __syncthreads();
    }

    // Epilogue: divide by l, write out
#pragma unroll
    for (int i = 0; i < 4; i++) {
        const int row = ty * 4 + i;
        const float inv = 1.0f / l_s[row];
        float4 r;
        r.x = o[i][0] * inv; r.y = o[i][1] * inv;
        r.z = o[i][2] * inv; r.w = o[i][3] * inv;
        *(float4*)&Og[base + (size_t)(q0 + row) * D_ + tx * 4] = r;
    }
}

// ---------------------------------------------------------------------------
extern "C" void kernel_launch(void* const* d_in, const int* in_sizes, int n_in,
                              void* d_out, int out_size)
{
    (void)in_sizes; (void)n_in; (void)out_size;
    const float* q   = (const float*)d_in[0];
    const float* k   = (const float*)d_in[1];
    const float* v   = (const float*)d_in[2];
    const float* Wq  = (const float*)d_in[3];
    const float* b_q = (const float*)d_in[4];
    const float* Wk  = (const float*)d_in[5];
    const float* b_k = (const float*)d_in[6];
    const float* Wv  = (const float*)d_in[7];
    const float* b_v = (const float*)d_in[8];
    const float* Wo  = (const float*)d_in[9];
    const float* b_o = (const float*)d_in[10];
    float* out = (float*)d_out;

    float *gQ, *gK, *gV, *gA;
    cudaGetSymbolAddress((void**)&gQ, g_Q);
    cudaGetSymbolAddress((void**)&gK, g_K);
    cudaGetSymbolAddress((void**)&gV, g_V);
    cudaGetSymbolAddress((void**)&gA, g_A);

    static const size_t attn_smem = ATTN_SMEM_FLOATS * sizeof(float); // 70400 B
    cudaFuncSetAttribute(attn_kernel,
                         cudaFuncAttributeMaxDynamicSharedMemorySize,
                         (int)attn_smem);

    dim3 gemm_grid(D_ / 64, M_ / 64);  // 16 x 128

    gemm_bias<<<gemm_grid, 256>>>(q, Wq, b_q, gQ, M_, D_, D_);
    gemm_bias<<<gemm_grid, 256>>>(k, Wk, b_k, gK, M_, D_, D_);
    gemm_bias<<<gemm_grid, 256>>>(v, Wv, b_v, gV, M_, D_, D_);

    dim3 attn_grid(T_ / 64, H_, B_);   // 32 x 16 x 4
    attn_kernel<<<attn_grid, 256, attn_smem>>>(gQ, gK, gV, gA);

    gemm_bias<<<gemm_grid, 256>>>(gA, Wo, b_o, out, M_, D_, D_);
}

// round 3
// speedup vs baseline: 1.6294x; 1.6294x over previous
#include <cuda_runtime.h>
#include <cstdint>
#include <math.h>

// Problem constants
#define B_  4
#define T_  2048
#define D_  1024
#define H_  16
#define DH_ 64
#define M_  (B_ * T_)   // 8192

// Scratch
__device__ float g_Q[(size_t)M_ * D_];
__device__ float g_K[(size_t)M_ * D_];
__device__ float g_V[(size_t)M_ * D_];
__device__ float g_A[(size_t)M_ * D_];
__device__ float g_Wt[4][(size_t)D_ * D_];   // transposed weights [N][K]

// ============================================================================
// Helpers
// ============================================================================
__device__ __forceinline__ uint32_t f2tf32(float x) {
    uint32_t u;
    asm("cvt.rna.tf32.f32 %0, %1;" : "=r"(u) : "f"(x));
    return u;
}

__device__ __forceinline__ void mma_tf32(float d[4], uint32_t a0, uint32_t a1,
                                         uint32_t a2, uint32_t a3,
                                         uint32_t b0, uint32_t b1) {
    asm volatile(
        "mma.sync.aligned.m16n8k8.row.col.f32.tf32.tf32.f32 "
        "{%0,%1,%2,%3}, {%4,%5,%6,%7}, {%8,%9}, {%0,%1,%2,%3};"
        : "+f"(d[0]), "+f"(d[1]), "+f"(d[2]), "+f"(d[3])
        : "r"(a0), "r"(a1), "r"(a2), "r"(a3), "r"(b0), "r"(b1));
}

// ============================================================================
// Weight transpose: out[n][k] = in[k][n], 1024x1024
// ============================================================================
__global__ __launch_bounds__(256) void transpose_k(const float* __restrict__ in,
                                                   float* __restrict__ out) {
    __shared__ float t[32][33];
    int x = blockIdx.x * 32 + threadIdx.x;
    int y0 = blockIdx.y * 32 + threadIdx.y;
#pragma unroll
    for (int i = 0; i < 32; i += 8)
        t[threadIdx.y + i][threadIdx.x] = in[(size_t)(y0 + i) * D_ + x];
    __syncthreads();
    x = blockIdx.y * 32 + threadIdx.x;
    y0 = blockIdx.x * 32 + threadIdx.y;
#pragma unroll
    for (int i = 0; i < 32; i += 8)
        out[(size_t)(y0 + i) * D_ + x] = t[threadIdx.x][threadIdx.y + i];
}

// ============================================================================
// tf32x3 GEMM via mma.sync: C[M,1024] = A[M,1024] @ Wt^T + bias
// A: [M][K] fp32 row-major;  Wt: [N][K] fp32 row-major (pre-transposed W).
// Block tile 128x128, BK=32, 256 threads = 8 warps (2m x 4n), warp tile 64x32.
// Each warp: 4 m-atoms (16) x 4 n-atoms (8), k-steps of 8.
// ============================================================================
#define GS 36   // padded row stride (uint32) for smem tiles
#define G_AH_OFF 0
#define G_AL_OFF (128 * GS)
#define G_BH_OFF (2 * 128 * GS)
#define G_BL_OFF (3 * 128 * GS)
#define G_SMEM (4 * 128 * GS * 4)   // 73728 bytes

__global__ __launch_bounds__(256) void gemm_tc(
    const float* __restrict__ Ag, const float* __restrict__ Wt,
    const float* __restrict__ bias, float* __restrict__ Cg)
{
    extern __shared__ uint32_t su[];
    uint32_t* Ah = su + G_AH_OFF;
    uint32_t* Al = su + G_AL_OFF;
    uint32_t* Bh = su + G_BH_OFF;
    uint32_t* Bl = su + G_BL_OFF;

    const int tid  = threadIdx.x;
    const int lane = tid & 31;
    const int wid  = tid >> 5;
    const int wm   = wid & 1;        // warp row (0..1) -> 64 rows each
    const int wn   = wid >> 1;       // warp col (0..3) -> 32 cols each
    const int row0 = blockIdx.y * 128;
    const int col0 = blockIdx.x * 128;

    const int lr = lane >> 2;        // 0..7
    const int lc = lane & 3;         // 0..3

    float d[4][4][4] = {};

    for (int k0 = 0; k0 < D_; k0 += 32) {
        // ---- Load + split A (128x32) and B (128x32) tiles ----
#pragma unroll
        for (int it = 0; it < 4; ++it) {
            const int f4 = tid + it * 256;     // 0..1023
            const int r  = f4 >> 3;            // 0..127
            const int c4 = f4 & 7;             // 0..7
            const float4 av = *(const float4*)&Ag[(size_t)(row0 + r) * D_ + k0 + c4 * 4];
            const float4 bv = *(const float4*)&Wt[(size_t)(col0 + r) * D_ + k0 + c4 * 4];
            uint4 h, l;
            h.x = f2tf32(av.x); h.y = f2tf32(av.y); h.z = f2tf32(av.z); h.w = f2tf32(av.w);
            l.x = f2tf32(av.x - __uint_as_float(h.x));
            l.y = f2tf32(av.y - __uint_as_float(h.y));
            l.z = f2tf32(av.z - __uint_as_float(h.z));
            l.w = f2tf32(av.w - __uint_as_float(h.w));
            *(uint4*)&Ah[r * GS + c4 * 4] = h;
            *(uint4*)&Al[r * GS + c4 * 4] = l;
            h.x = f2tf32(bv.x); h.y = f2tf32(bv.y); h.z = f2tf32(bv.z); h.w = f2tf32(bv.w);
            l.x = f2tf32(bv.x - __uint_as_float(h.x));
            l.y = f2tf32(bv.y - __uint_as_float(h.y));
            l.z = f2tf32(bv.z - __uint_as_float(h.z));
            l.w = f2tf32(bv.w - __uint_as_float(h.w));
            *(uint4*)&Bh[r * GS + c4 * 4] = h;
            *(uint4*)&Bl[r * GS + c4 * 4] = l;
        }
        __syncthreads();

        // ---- Compute: 4 k-steps of 8 ----
#pragma unroll
        for (int ks = 0; ks < 4; ++ks) {
            const int kb = ks * 8;
            uint32_t ah[4][4], al[4][4];
#pragma unroll
            for (int i = 0; i < 4; ++i) {
                const int r = wm * 64 + i * 16 + lr;
                ah[i][0] = Ah[r * GS + kb + lc];
                ah[i][1] = Ah[(r + 8) * GS + kb + lc];
                ah[i][2] = Ah[r * GS + kb + lc + 4];
                ah[i][3] = Ah[(r + 8) * GS + kb + lc + 4];
                al[i][0] = Al[r * GS + kb + lc];
                al[i][1] = Al[(r + 8) * GS + kb + lc];
                al[i][2] = Al[r * GS + kb + lc + 4];
                al[i][3] = Al[(r + 8) * GS + kb + lc + 4];
            }
            uint32_t bh[4][2], bl[4][2];
#pragma unroll
            for (int j = 0; j < 4; ++j) {
                const int n = wn * 32 + j * 8 + lr;
                bh[j][0] = Bh[n * GS + kb + lc];
                bh[j][1] = Bh[n * GS + kb + lc + 4];
                bl[j][0] = Bl[n * GS + kb + lc];
                bl[j][1] = Bl[n * GS + kb + lc + 4];
            }
#pragma unroll
            for (int i = 0; i < 4; ++i)
#pragma unroll
                for (int j = 0; j < 4; ++j) {
                    mma_tf32(d[i][j], ah[i][0], ah[i][1], ah[i][2], ah[i][3],
                             bh[j][0], bh[j][1]);
                    mma_tf32(d[i][j], ah[i][0], ah[i][1], ah[i][2], ah[i][3],
                             bl[j][0], bl[j][1]);
                    mma_tf32(d[i][j], al[i][0], al[i][1], al[i][2], al[i][3],
                             bh[j][0], bh[j][1]);
                }
        }
        __syncthreads();
    }

    // ---- Epilogue: bias + store ----
#pragma unroll
    for (int i = 0; i < 4; ++i) {
        const int grow = row0 + wm * 64 + i * 16 + lr;
#pragma unroll
        for (int j = 0; j < 4; ++j) {
            const int gcol = col0 + wn * 32 + j * 8 + lc * 2;
            const float2 bb = *(const float2*)&bias[gcol];
            float2 r0v, r1v;
            r0v.x = d[i][j][0] + bb.x; r0v.y = d[i][j][1] + bb.y;
            r1v.x = d[i][j][2] + bb.x; r1v.y = d[i][j][3] + bb.y;
            *(float2*)&Cg[(size_t)grow * D_ + gcol] = r0v;
            *(float2*)&Cg[(size_t)(grow + 8) * D_ + gcol] = r1v;
        }
    }
}

// ============================================================================
// Flash attention (fp32): swizzled smem + register online softmax.
// Block = 64 q-rows x 1 head x 1 batch, 256 threads, 32 k-tiles of 64.
// ============================================================================
#define ATTN_SMEM ((3 * 64 * 64 + 64 * 68) * 4)

__global__ __launch_bounds__(256) void attn_kernel(
    const float* __restrict__ Qg, const float* __restrict__ Kg,
    const float* __restrict__ Vg, float* __restrict__ Og)
{
    extern __shared__ float sf[];
    float* Qs = sf;                  // [64][64] swizzled
    float* Ks = Qs + 64 * 64;        // [64][64] swizzled
    float* Ss = Ks + 64 * 64;        // [64][64] swizzled
    float* Vs = Ss + 64 * 64;        // [64][68] plain

    const int tid = threadIdx.x;
    const int tx = tid & 15;
    const int ty = tid >> 4;
    const int q0 = blockIdx.x * 64;
    const int h  = blockIdx.y;
    const int b  = blockIdx.z;
    const size_t base = (size_t)b * T_ * D_ + (size_t)h * DH_;

    // Load Q (swizzled)
    {
        const int cb = tid & 15;
        const int r0 = tid >> 4;
#pragma unroll
        for (int rr = 0; rr < 4; rr++) {
            const int row = r0 + rr * 16;
            *(float4*)&Qs[row * 64 + ((cb ^ (row >> 2)) & 15) * 4] =
                *(const float4*)&Qg[base + (size_t)(q0 + row) * D_ + cb * 4];
        }
    }

    float o[4][4] = {};
    float m[4] = {-1e30f, -1e30f, -1e30f, -1e30f};
    float l[4] = {};
    __syncthreads();

    for (int s0 = 0; s0 < T_; s0 += 64) {
        // Load K (swizzled), V (plain)
        {
            const int cb = tid & 15;
            const int r0 = tid >> 4;
#pragma unroll
            for (int rr = 0; rr < 4; rr++) {
                const int row = r0 + rr * 16;
                *(float4*)&Ks[row * 64 + ((cb ^ (row >> 2)) & 15) * 4] =
                    *(const float4*)&Kg[base + (size_t)(s0 + row) * D_ + cb * 4];
                *(float4*)&Vs[row * 68 + cb * 4] =
                    *(const float4*)&Vg[base + (size_t)(s0 + row) * D_ + cb * 4];
            }
        }
        __syncthreads();

        // S = Q K^T (swizzled, mostly conflict-free)
        float s[4][4] = {};
#pragma unroll
        for (int d4 = 0; d4 < 16; d4++) {
            float4 q4[4], k4[4];
#pragma unroll
            for (int i = 0; i < 4; i++)
                q4[i] = *(const float4*)&Qs[(ty * 4 + i) * 64 + ((d4 ^ ty) & 15) * 4];
#pragma unroll
            for (int j = 0; j < 4; j++)
                k4[j] = *(const float4*)&Ks[(tx * 4 + j) * 64 + ((d4 ^ tx) & 15) * 4];
#pragma unroll
            for (int i = 0; i < 4; i++)
#pragma unroll
                for (int j = 0; j < 4; j++)
                    s[i][j] += q4[i].x * k4[j].x + q4[i].y * k4[j].y +
                               q4[i].z * k4[j].z + q4[i].w * k4[j].w;
        }

        // Register online softmax (reduce across 16-lane tx group)
        float corr[4];
#pragma unroll
        for (int i = 0; i < 4; i++) {
            float mx = fmaxf(fmaxf(s[i][0], s[i][1]), fmaxf(s[i][2], s[i][3])) * 0.125f;
#pragma unroll
            for (int off = 1; off < 16; off <<= 1)
                mx = fmaxf(mx, __shfl_xor_sync(0xffffffffu, mx, off));
            const float mn = fmaxf(m[i], mx);
            corr[i] = __expf(m[i] - mn);
            float rs = 0.0f;
#pragma unroll
            for (int j = 0; j < 4; j++) {
                const float p = __expf(s[i][j] * 0.125f - mn);
                s[i][j] = p;
                rs += p;
            }
#pragma unroll
            for (int off = 1; off < 16; off <<= 1)
                rs += __shfl_xor_sync(0xffffffffu, rs, off);
            l[i] = l[i] * corr[i] + rs;
            m[i] = mn;
#pragma unroll
            for (int j = 0; j < 4; j++) o[i][j] *= corr[i];
        }

        // Write P to Ss (swizzled)
#pragma unroll
        for (int i = 0; i < 4; i++)
            *(float4*)&Ss[(ty * 4 + i) * 64 + ((tx ^ ty) & 15) * 4] =
                make_float4(s[i][0], s[i][1], s[i][2], s[i][3]);
        __syncthreads();

        // O += P @ V
#pragma unroll
        for (int s4 = 0; s4 < 16; s4++) {
            float p[4][4];
#pragma unroll
            for (int i = 0; i < 4; i++) {
                const float4 p4 = *(const float4*)&Ss[(ty * 4 + i) * 64 + ((s4 ^ ty) & 15) * 4];
                p[i][0] = p4.x; p[i][1] = p4.y; p[i][2] = p4.z; p[i][3] = p4.w;
            }
#pragma unroll
            for (int u = 0; u < 4; u++) {
                const float4 v4 = *(const float4*)&Vs[(s4 * 4 + u) * 68 + tx * 4];
#pragma unroll
                for (int i = 0; i < 4; i++) {
                    o[i][0] += p[i][u] * v4.x;
                    o[i][1] += p[i][u] * v4.y;
                    o[i][2] += p[i][u] * v4.z;
                    o[i][3] += p[i][u] * v4.w;
                }
            }
        }
        __syncthreads();
    }

    // Epilogue
#pragma unroll
    for (int i = 0; i < 4; i++) {
        const int row = ty * 4 + i;
        const float inv = 1.0f / l[i];
        float4 r;
        r.x = o[i][0] * inv; r.y = o[i][1] * inv;
        r.z = o[i][2] * inv; r.w = o[i][3] * inv;
        *(float4*)&Og[base + (size_t)(q0 + row) * D_ + tx * 4] = r;
    }
}

// ============================================================================
extern "C" void kernel_launch(void* const* d_in, const int* in_sizes, int n_in,
                              void* d_out, int out_size)
{
    (void)in_sizes; (void)n_in; (void)out_size;
    const float* q   = (const float*)d_in[0];
    const float* k   = (const float*)d_in[1];
    const float* v   = (const float*)d_in[2];
    const float* Wq  = (const float*)d_in[3];
    const float* b_q = (const float*)d_in[4];
    const float* Wk  = (const float*)d_in[5];
    const float* b_k = (const float*)d_in[6];
    const float* Wv  = (const float*)d_in[7];
    const float* b_v = (const float*)d_in[8];
    const float* Wo  = (const float*)d_in[9];
    const float* b_o = (const float*)d_in[10];
    float* out = (float*)d_out;

    float *gQ, *gK, *gV, *gA, *gWt;
    cudaGetSymbolAddress((void**)&gQ, g_Q);
    cudaGetSymbolAddress((void**)&gK, g_K);
    cudaGetSymbolAddress((void**)&gV, g_V);
    cudaGetSymbolAddress((void**)&gA, g_A);
    cudaGetSymbolAddress((void**)&gWt, g_Wt);

    cudaFuncSetAttribute(gemm_tc, cudaFuncAttributeMaxDynamicSharedMemorySize, G_SMEM);
    cudaFuncSetAttribute(attn_kernel, cudaFuncAttributeMaxDynamicSharedMemorySize, ATTN_SMEM);

    // Transpose weights
    dim3 tgrid(D_ / 32, D_ / 32), tblk(32, 8);
    transpose_k<<<tgrid, tblk>>>(Wq, gWt + 0 * (size_t)D_ * D_);
    transpose_k<<<tgrid, tblk>>>(Wk, gWt + 1 * (size_t)D_ * D_);
    transpose_k<<<tgrid, tblk>>>(Wv, gWt + 2 * (size_t)D_ * D_);
    transpose_k<<<tgrid, tblk>>>(Wo, gWt + 3 * (size_t)D_ * D_);

    // Projections on mma.sync tf32x3
    dim3 ggrid(D_ / 128, M_ / 128);  // 8 x 64
    gemm_tc<<<ggrid, 256, G_SMEM>>>(q, gWt + 0 * (size_t)D_ * D_, b_q, gQ);
    gemm_tc<<<ggrid, 256, G_SMEM>>>(k, gWt + 1 * (size_t)D_ * D_, b_k, gK);
    gemm_tc<<<ggrid, 256, G_SMEM>>>(v, gWt + 2 * (size_t)D_ * D_, b_v, gV);

    dim3 attn_grid(T_ / 64, H_, B_);
    attn_kernel<<<attn_grid, 256, ATTN_SMEM>>>(gQ, gK, gV, gA);

    gemm_tc<<<ggrid, 256, G_SMEM>>>(gA, gWt + 3 * (size_t)D_ * D_, b_o, out);
}

// round 4
// speedup vs baseline: 3.6242x; 2.2242x over previous
#include <cuda_runtime.h>
#include <cuda_bf16.h>
#include <cstdint>
#include <math.h>

typedef __nv_bfloat16 bf16;

// Problem constants
#define B_  4
#define T_  2048
#define D_  1024
#define H_  16
#define DH_ 64
#define M_  (B_ * T_)   // 8192
#define DD_ ((size_t)D_ * D_)
#define MD_ ((size_t)M_ * D_)

// Scratch (bf16 h/l pairs everywhere)
__device__ bf16 g_in6[6][MD_];   // qh,ql,kh,kl,vh,vl (split inputs)
__device__ bf16 g_qkv[6][MD_];   // Qh,Ql,Kh,Kl,Vh,Vl (projected)
__device__ bf16 g_att[2][MD_];   // attention out h,l
__device__ bf16 g_w8[8][DD_];    // Wq_h,Wq_l,Wk_h,Wk_l,Wv_h,Wv_l,Wo_h,Wo_l (transposed [N][K])

// ============================================================================
// PTX helpers
// ============================================================================
__device__ __forceinline__ uint32_t smem_u32(const void* p) {
    uint32_t a;
    asm("{ .reg .u64 t; cvta.to.shared.u64 t, %1; cvt.u32.u64 %0, t; }" : "=r"(a) : "l"(p));
    return a;
}
__device__ __forceinline__ void mma_bf16(float* d, const uint32_t* a, uint32_t b0, uint32_t b1) {
    asm volatile(
        "mma.sync.aligned.m16n8k16.row.col.f32.bf16.bf16.f32 "
        "{%0,%1,%2,%3}, {%4,%5,%6,%7}, {%8,%9}, {%0,%1,%2,%3};"
        : "+f"(d[0]), "+f"(d[1]), "+f"(d[2]), "+f"(d[3])
        : "r"(a[0]), "r"(a[1]), "r"(a[2]), "r"(a[3]), "r"(b0), "r"(b1));
}
__device__ __forceinline__ void ldm4(uint32_t* r, uint32_t a) {
    asm volatile("ldmatrix.sync.aligned.m8n8.x4.shared.b16 {%0,%1,%2,%3}, [%4];"
                 : "=r"(r[0]), "=r"(r[1]), "=r"(r[2]), "=r"(r[3]) : "r"(a));
}
__device__ __forceinline__ void ldm4t(uint32_t* r, uint32_t a) {
    asm volatile("ldmatrix.sync.aligned.m8n8.x4.trans.shared.b16 {%0,%1,%2,%3}, [%4];"
                 : "=r"(r[0]), "=r"(r[1]), "=r"(r[2]), "=r"(r[3]) : "r"(a));
}
__device__ __forceinline__ void cp16(uint32_t dst, const void* src) {
    asm volatile("cp.async.cg.shared.global [%0], [%1], 16;" :: "r"(dst), "l"(src));
}
#define CP_COMMIT() asm volatile("cp.async.commit_group;" ::: "memory")
#define CP_WAIT0()  asm volatile("cp.async.wait_group 0;" ::: "memory")
#define CP_WAIT1()  asm volatile("cp.async.wait_group 1;" ::: "memory")

__device__ __forceinline__ uint32_t pk(float a, float b) {
    __nv_bfloat162 t = __floats2bfloat162_rn(a, b);
    return *reinterpret_cast<uint32_t*>(&t);
}
// split (a,b) into packed bf16 high + residual-low words
__device__ __forceinline__ void splitpk(float a, float b, uint32_t& hh, uint32_t& ll) {
    float ah = __bfloat162float(__float2bfloat16_rn(a));
    float bh = __bfloat162float(__float2bfloat16_rn(b));
    hh = pk(ah, bh);
    ll = pk(a - ah, b - bh);
}

// ============================================================================
// transpose + split: out_[h|l][n][k] = split(in[k][n]), 1024x1024
// ============================================================================
__global__ __launch_bounds__(256) void transpose_split(const float* __restrict__ in,
                                                       bf16* __restrict__ oh,
                                                       bf16* __restrict__ ol) {
    __shared__ float t[32][33];
    int x = blockIdx.x * 32 + threadIdx.x;
    int y0 = blockIdx.y * 32 + threadIdx.y;
#pragma unroll
    for (int i = 0; i < 32; i += 8)
        t[threadIdx.y + i][threadIdx.x] = in[(size_t)(y0 + i) * D_ + x];
    __syncthreads();
    x = blockIdx.y * 32 + threadIdx.x;
    y0 = blockIdx.x * 32 + threadIdx.y;
#pragma unroll
    for (int i = 0; i < 32; i += 8) {
        float v = t[threadIdx.x][threadIdx.y + i];
        bf16 h = __float2bfloat16_rn(v);
        oh[(size_t)(y0 + i) * D_ + x] = h;
        ol[(size_t)(y0 + i) * D_ + x] = __float2bfloat16_rn(v - __bfloat162float(h));
    }
}

// ============================================================================
// split fp32 -> bf16 h/l, vectorized
// ============================================================================
__global__ __launch_bounds__(256) void split2(const float4* __restrict__ in,
                                              uint32_t* __restrict__ oh,
                                              uint32_t* __restrict__ ol, int n4) {
    int i = blockIdx.x * 256 + threadIdx.x;
    if (i >= n4) return;
    float4 v = in[i];
    uint32_t h0, l0, h1, l1;
    splitpk(v.x, v.y, h0, l0);
    splitpk(v.z, v.w, h1, l1);
    oh[i * 2] = h0; oh[i * 2 + 1] = h1;
    ol[i * 2] = l0; ol[i * 2 + 1] = l1;
}

// ============================================================================
// bf16x3 GEMM: C[M,1024] = (A @ Wt^T + bias) * scale
// A = Ah+Al [M][K] bf16; Wt = Bh+Bl [N][K] bf16. Block 128x128, BK=32,
// 8 warps (2m x 4n), warp tile 64x32, cp.async double-buffered.
// Output: fp32 (outF) or split bf16 (outH/outL).
// ============================================================================
#define GKS 40                   // smem k-stride (bf16)
#define GTILE (128 * GKS)        // bf16 per tile buffer
#define G_SMEM (2 * 4 * GTILE * 2)  // 81920 bytes

__global__ __launch_bounds__(256) void gemm_bf3(
    const bf16* __restrict__ Ah, const bf16* __restrict__ Al,
    const bf16* __restrict__ Bh, const bf16* __restrict__ Bl,
    const float* __restrict__ bias, float scale,
    float* __restrict__ outF, bf16* __restrict__ outH, bf16* __restrict__ outL)
{
    extern __shared__ bf16 sb[];
    const uint32_t sbase = smem_u32(sb);
    const int tid = threadIdx.x, lane = tid & 31, wid = tid >> 5;
    const int wm = wid & 1, wn = wid >> 1;
    const int row0 = blockIdx.y * 128, col0 = blockIdx.x * 128;

    float d[4][4][4] = {};

    auto load_stage = [&](int s, int kt) {
        const bf16* srcs[4] = {Ah, Al, Bh, Bl};
        const int rb[4] = {row0, row0, col0, col0};
#pragma unroll
        for (int bi = 0; bi < 4; ++bi) {
#pragma unroll
            for (int it = 0; it < 2; ++it) {
                int ch = tid + it * 256;              // 0..511
                int r = ch >> 2, c8 = ch & 3;
                const bf16* g = srcs[bi] + (size_t)(rb[bi] + r) * D_ + kt * 32 + c8 * 8;
                cp16(sbase + ((s * 4 + bi) * GTILE + r * GKS + c8 * 8) * 2, g);
            }
        }
    };

    auto compute_stage = [&](int s) {
        const uint32_t aB  = sbase + (s * 4 + 0) * GTILE * 2;
        const uint32_t alB = sbase + (s * 4 + 1) * GTILE * 2;
        const uint32_t bB  = sbase + (s * 4 + 2) * GTILE * 2;
        const uint32_t blB = sbase + (s * 4 + 3) * GTILE * 2;
        const int l15 = lane & 15, l7 = lane & 7;
        const int aro = (lane & 16) ? 8 : 0;
        const int bko = (lane & 8) ? 8 : 0;
        const int bro = (lane & 16) ? 8 : 0;
#pragma unroll
        for (int kh2 = 0; kh2 < 2; ++kh2) {
            uint32_t ah[4][4], al[4][4], bh[2][4], bl[2][4];
#pragma unroll
            for (int i = 0; i < 4; ++i) {
                uint32_t off = (uint32_t)((wm * 64 + i * 16 + l15) * GKS + kh2 * 16 + aro) * 2;
                ldm4(ah[i], aB + off);
                ldm4(al[i], alB + off);
            }
#pragma unroll
            for (int nb = 0; nb < 2; ++nb) {
                uint32_t off = (uint32_t)((wn * 32 + nb * 16 + l7 + bro) * GKS + kh2 * 16 + bko) * 2;
                ldm4(bh[nb], bB + off);
                ldm4(bl[nb], blB + off);
            }
#pragma unroll
            for (int i = 0; i < 4; ++i)
#pragma unroll
                for (int j = 0; j < 4; ++j) {
                    const int nb = j >> 1, hf = (j & 1) * 2;
                    mma_bf16(d[i][j], ah[i], bh[nb][hf], bh[nb][hf + 1]);
                    mma_bf16(d[i][j], ah[i], bl[nb][hf], bl[nb][hf + 1]);
                    mma_bf16(d[i][j], al[i], bh[nb][hf], bh[nb][hf + 1]);
                }
        }
    };

    load_stage(0, 0); CP_COMMIT();
    for (int kt = 0; kt < 32; ++kt) {
        if (kt + 1 < 32) { load_stage((kt + 1) & 1, kt + 1); CP_COMMIT(); CP_WAIT1(); }
        else             { CP_WAIT0(); }
        __syncthreads();
        compute_stage(kt & 1);
        __syncthreads();
    }

    // Epilogue
    const int lr = lane >> 2, lc = lane & 3;
#pragma unroll
    for (int i = 0; i < 4; ++i) {
        const int r0g = row0 + wm * 64 + i * 16 + lr;
#pragma unroll
        for (int j = 0; j < 4; ++j) {
            const int cg = col0 + wn * 32 + j * 8 + lc * 2;
            const float2 bb = *(const float2*)&bias[cg];
            const float v0 = (d[i][j][0] + bb.x) * scale;
            const float v1 = (d[i][j][1] + bb.y) * scale;
            const float v2 = (d[i][j][2] + bb.x) * scale;
            const float v3 = (d[i][j][3] + bb.y) * scale;
            if (outF) {
                *(float2*)&outF[(size_t)r0g * D_ + cg] = make_float2(v0, v1);
                *(float2*)&outF[(size_t)(r0g + 8) * D_ + cg] = make_float2(v2, v3);
            } else {
                uint32_t hh, ll;
                splitpk(v0, v1, hh, ll);
                *(uint32_t*)(outH + (size_t)r0g * D_ + cg) = hh;
                *(uint32_t*)(outL + (size_t)r0g * D_ + cg) = ll;
                splitpk(v2, v3, hh, ll);
                *(uint32_t*)(outH + (size_t)(r0g + 8) * D_ + cg) = hh;
                *(uint32_t*)(outL + (size_t)(r0g + 8) * D_ + cg) = ll;
            }
        }
    }
}

// ============================================================================
// Flash attention on bf16x3 mma.sync. Block = 64 q-rows x head x batch,
// 128 threads (4 warps, 16 q-rows each), 32 kv-tiles of 64.
// Q pre-scaled by 1/8 at projection time.
// ============================================================================
#define AST 72                  // smem row stride (bf16)
#define ABUF (64 * AST)         // bf16 per buffer
#define A_SMEM (4 * ABUF * 2)   // 36864 bytes

__global__ __launch_bounds__(128) void attn_bf3(
    const bf16* __restrict__ Qh, const bf16* __restrict__ Ql,
    const bf16* __restrict__ Kh, const bf16* __restrict__ Kl,
    const bf16* __restrict__ Vh, const bf16* __restrict__ Vl,
    bf16* __restrict__ Oh, bf16* __restrict__ Ol)
{
    extern __shared__ bf16 sa_[];
    const uint32_t sbase = smem_u32(sa_);
    const int tid = threadIdx.x, lane = tid & 31, wq = tid >> 5;
    const int q0 = blockIdx.x * 64, hd = blockIdx.y, bb = blockIdx.z;
    const size_t gbase = ((size_t)bb * T_) * D_ + (size_t)hd * 64;

    // ---- Load Q tile into buffers 0/1, extract A-fragments ----
    {
        const bf16* s0p = Qh + gbase + (size_t)q0 * D_;
        const bf16* s1p = Ql + gbase + (size_t)q0 * D_;
#pragma unroll
        for (int it = 0; it < 4; ++it) {
            const int ch = tid + it * 128;
            const int r = ch >> 3, c8 = ch & 7;
            cp16(sbase + (0 * ABUF + r * AST + c8 * 8) * 2, s0p + (size_t)r * D_ + c8 * 8);
            cp16(sbase + (1 * ABUF + r * AST + c8 * 8) * 2, s1p + (size_t)r * D_ + c8 * 8);
        }
        CP_COMMIT(); CP_WAIT0();
        __syncthreads();
    }
    uint32_t qh[4][4], ql[4][4];
    {
        const int l15 = lane & 15;
        const int ao = (lane & 16) ? 8 : 0;
#pragma unroll
        for (int ka = 0; ka < 4; ++ka) {
            const uint32_t off = (uint32_t)((wq * 16 + l15) * AST + ka * 16 + ao) * 2;
            ldm4(qh[ka], sbase + 0 * ABUF * 2 + off);
            ldm4(ql[ka], sbase + 1 * ABUF * 2 + off);
        }
    }
    __syncthreads();

    float O[8][4] = {};
    float m0 = -1e30f, m1 = -1e30f, l0 = 0.f, l1 = 0.f;

    for (int s0 = 0; s0 < T_; s0 += 64) {
        // ---- Load K/V h,l tiles ----
        {
            const bf16* srcs[4] = {Kh, Kl, Vh, Vl};
#pragma unroll
            for (int bi = 0; bi < 4; ++bi) {
                const bf16* g0 = srcs[bi] + gbase + (size_t)s0 * D_;
#pragma unroll
                for (int it = 0; it < 4; ++it) {
                    const int ch = tid + it * 128;
                    const int r = ch >> 3, c8 = ch & 7;
                    cp16(sbase + (bi * ABUF + r * AST + c8 * 8) * 2,
                         g0 + (size_t)r * D_ + c8 * 8);
                }
            }
            CP_COMMIT(); CP_WAIT0();
            __syncthreads();
        }

        // ---- S = Q K^T (bf16x3) ----
        float S[8][4] = {};
        {
            const int l7 = lane & 7;
            const int bro = (lane & 16) ? 8 : 0;
            const int bko = (lane & 8) ? 8 : 0;
#pragma unroll
            for (int ka = 0; ka < 4; ++ka)
#pragma unroll
                for (int nb = 0; nb < 4; ++nb) {
                    const uint32_t off =
                        (uint32_t)((nb * 16 + l7 + bro) * AST + ka * 16 + bko) * 2;
                    uint32_t kh[4], kl[4];
                    ldm4(kh, sbase + 0 * ABUF * 2 + off);
                    ldm4(kl, sbase + 1 * ABUF * 2 + off);
                    mma_bf16(S[2 * nb],     qh[ka], kh[0], kh[1]);
                    mma_bf16(S[2 * nb],     qh[ka], kl[0], kl[1]);
                    mma_bf16(S[2 * nb],     ql[ka], kh[0], kh[1]);
                    mma_bf16(S[2 * nb + 1], qh[ka], kh[2], kh[3]);
                    mma_bf16(S[2 * nb + 1], qh[ka], kl[2], kl[3]);
                    mma_bf16(S[2 * nb + 1], ql[ka], kh[2], kh[3]);
                }
        }

        // ---- Online softmax (register, 4-lane row groups) ----
        float mx0 = -1e30f, mx1 = -1e30f;
#pragma unroll
        for (int j = 0; j < 8; ++j) {
            mx0 = fmaxf(mx0, fmaxf(S[j][0], S[j][1]));
            mx1 = fmaxf(mx1, fmaxf(S[j][2], S[j][3]));
        }
        mx0 = fmaxf(mx0, __shfl_xor_sync(0xffffffffu, mx0, 1));
        mx0 = fmaxf(mx0, __shfl_xor_sync(0xffffffffu, mx0, 2));
        mx1 = fmaxf(mx1, __shfl_xor_sync(0xffffffffu, mx1, 1));
        mx1 = fmaxf(mx1, __shfl_xor_sync(0xffffffffu, mx1, 2));
        const float mn0 = fmaxf(m0, mx0), mn1 = fmaxf(m1, mx1);
        const float c0 = __expf(m0 - mn0), c1 = __expf(m1 - mn1);

        uint32_t ph[4][4], pl[4][4];
        float r0 = 0.f, r1 = 0.f;
#pragma unroll
        for (int j = 0; j < 8; ++j) {
            const float p0 = __expf(S[j][0] - mn0);
            const float p1 = __expf(S[j][1] - mn0);
            const float p2 = __expf(S[j][2] - mn1);
            const float p3 = __expf(S[j][3] - mn1);
            r0 += p0 + p1; r1 += p2 + p3;
            const int t = j >> 1, o = (j & 1) * 2;
            uint32_t hh, ll;
            splitpk(p0, p1, hh, ll); ph[t][o] = hh;     pl[t][o] = ll;
            splitpk(p2, p3, hh, ll); ph[t][o + 1] = hh; pl[t][o + 1] = ll;
        }
        r0 += __shfl_xor_sync(0xffffffffu, r0, 1);
        r0 += __shfl_xor_sync(0xffffffffu, r0, 2);
        r1 += __shfl_xor_sync(0xffffffffu, r1, 1);
        r1 += __shfl_xor_sync(0xffffffffu, r1, 2);
        l0 = l0 * c0 + r0; l1 = l1 * c1 + r1;
        m0 = mn0; m1 = mn1;
#pragma unroll
        for (int j = 0; j < 8; ++j) {
            O[j][0] *= c0; O[j][1] *= c0; O[j][2] *= c1; O[j][3] *= c1;
        }

        // ---- O += P V (bf16x3, V via ldmatrix.trans) ----
        {
            const int l15 = lane & 15;
            const int no = (lane & 16) ? 8 : 0;
#pragma unroll
            for (int kt = 0; kt < 4; ++kt)
#pragma unroll
                for (int nb = 0; nb < 4; ++nb) {
                    const uint32_t off =
                        (uint32_t)((kt * 16 + l15) * AST + nb * 16 + no) * 2;
                    uint32_t vh[4], vl[4];
                    ldm4t(vh, sbase + 2 * ABUF * 2 + off);
                    ldm4t(vl, sbase + 3 * ABUF * 2 + off);
                    mma_bf16(O[2 * nb],     ph[kt], vh[0], vh[1]);
                    mma_bf16(O[2 * nb],     ph[kt], vl[0], vl[1]);
                    mma_bf16(O[2 * nb],     pl[kt], vh[0], vh[1]);
                    mma_bf16(O[2 * nb + 1], ph[kt], vh[2], vh[3]);
                    mma_bf16(O[2 * nb + 1], ph[kt], vl[2], vl[3]);
                    mma_bf16(O[2 * nb + 1], pl[kt], vh[2], vh[3]);
                }
        }
        __syncthreads();
    }

    // ---- Epilogue: normalize, split to bf16 h/l ----
    const int lr = lane >> 2, lc = lane & 3;
    const float inv0 = 1.f / l0, inv1 = 1.f / l1;
    const size_t rA = (size_t)bb * T_ + q0 + wq * 16 + lr;
    const size_t rB = rA + 8;
#pragma unroll
    for (int j = 0; j < 8; ++j) {
        const int cg = hd * 64 + j * 8 + lc * 2;
        uint32_t hh, ll;
        splitpk(O[j][0] * inv0, O[j][1] * inv0, hh, ll);
        *(uint32_t*)(Oh + rA * D_ + cg) = hh;
        *(uint32_t*)(Ol + rA * D_ + cg) = ll;
        splitpk(O[j][2] * inv1, O[j][3] * inv1, hh, ll);
        *(uint32_t*)(Oh + rB * D_ + cg) = hh;
        *(uint32_t*)(Ol + rB * D_ + cg) = ll;
    }
}

// ============================================================================
extern "C" void kernel_launch(void* const* d_in, const int* in_sizes, int n_in,
                              void* d_out, int out_size)
{
    (void)in_sizes; (void)n_in; (void)out_size;
    const float* q   = (const float*)d_in[0];
    const float* k   = (const float*)d_in[1];
    const float* v   = (const float*)d_in[2];
    const float* Wq  = (const float*)d_in[3];
    const float* b_q = (const float*)d_in[4];
    const float* Wk  = (const float*)d_in[5];
    const float* b_k = (const float*)d_in[6];
    const float* Wv  = (const float*)d_in[7];
    const float* b_v = (const float*)d_in[8];
    const float* Wo  = (const float*)d_in[9];
    const float* b_o = (const float*)d_in[10];
    float* out = (float*)d_out;

    bf16 *in6, *qkv, *att, *w8;
    cudaGetSymbolAddress((void**)&in6, g_in6);
    cudaGetSymbolAddress((void**)&qkv, g_qkv);
    cudaGetSymbolAddress((void**)&att, g_att);
    cudaGetSymbolAddress((void**)&w8,  g_w8);

    cudaFuncSetAttribute(gemm_bf3, cudaFuncAttributeMaxDynamicSharedMemorySize, G_SMEM);
    cudaFuncSetAttribute(attn_bf3, cudaFuncAttributeMaxDynamicSharedMemorySize, A_SMEM);

    // Transpose + split weights
    dim3 tgrid(32, 32), tblk(32, 8);
    transpose_split<<<tgrid, tblk>>>(Wq, w8 + 0 * DD_, w8 + 1 * DD_);
    transpose_split<<<tgrid, tblk>>>(Wk, w8 + 2 * DD_, w8 + 3 * DD_);
    transpose_split<<<tgrid, tblk>>>(Wv, w8 + 4 * DD_, w8 + 5 * DD_);
    transpose_split<<<tgrid, tblk>>>(Wo, w8 + 6 * DD_, w8 + 7 * DD_);

    // Split activations
    const int n4 = (int)(MD_ / 4);
    split2<<<n4 / 256, 256>>>((const float4*)q, (uint32_t*)(in6 + 0 * MD_), (uint32_t*)(in6 + 1 * MD_), n4);
    split2<<<n4 / 256, 256>>>((const float4*)k, (uint32_t*)(in6 + 2 * MD_), (uint32_t*)(in6 + 3 * MD_), n4);
    split2<<<n4 / 256, 256>>>((const float4*)v, (uint32_t*)(in6 + 4 * MD_), (uint32_t*)(in6 + 5 * MD_), n4);

    // Projections (Q pre-scaled by 1/sqrt(DH)=0.125)
    dim3 ggrid(D_ / 128, M_ / 128);  // 8 x 64
    gemm_bf3<<<ggrid, 256, G_SMEM>>>(in6 + 0 * MD_, in6 + 1 * MD_, w8 + 0 * DD_, w8 + 1 * DD_,
                                     b_q, 0.125f, nullptr, qkv + 0 * MD_, qkv + 1 * MD_);
    gemm_bf3<<<ggrid, 256, G_SMEM>>>(in6 + 2 * MD_, in6 + 3 * MD_, w8 + 2 * DD_, w8 + 3 * DD_,
                                     b_k, 1.0f, nullptr, qkv + 2 * MD_, qkv + 3 * MD_);
    gemm_bf3<<<ggrid, 256, G_SMEM>>>(in6 + 4 * MD_, in6 + 5 * MD_, w8 + 4 * DD_, w8 + 5 * DD_,
                                     b_v, 1.0f, nullptr, qkv + 4 * MD_, qkv + 5 * MD_);

    // Attention
    dim3 agrid(T_ / 64, H_, B_);
    attn_bf3<<<agrid, 128, A_SMEM>>>(qkv + 0 * MD_, qkv + 1 * MD_, qkv + 2 * MD_,
                                     qkv + 3 * MD_, qkv + 4 * MD_, qkv + 5 * MD_,
                                     att + 0 * MD_, att + 1 * MD_);

    // Output projection -> fp32
    gemm_bf3<<<ggrid, 256, G_SMEM>>>(att + 0 * MD_, att + 1 * MD_, w8 + 6 * DD_, w8 + 7 * DD_,
                                     b_o, 1.0f, out, nullptr, nullptr);
}

// round 5
// speedup vs baseline: 3.8718x; 1.0683x over previous
#include <cuda_runtime.h>
#include <cuda_bf16.h>
#include <cstdint>
#include <math.h>

typedef __nv_bfloat16 bf16;

// Problem constants
#define B_  4
#define T_  2048
#define D_  1024
#define H_  16
#define DH_ 64
#define M_  (B_ * T_)   // 8192
#define DD_ ((size_t)D_ * D_)
#define MD_ ((size_t)M_ * D_)

// Scratch (bf16 h/l pairs everywhere)
__device__ bf16 g_in6[6][MD_];   // qh,ql,kh,kl,vh,vl (split inputs)
__device__ bf16 g_qkv[6][MD_];   // Qh,Ql,Kh,Kl,Vh,Vl (projected)
__device__ bf16 g_att[2][MD_];   // attention out h,l
__device__ bf16 g_w8[8][DD_];    // Wq,Wk,Wv,Wo h/l (transposed [N][K])

// ============================================================================
// PTX helpers
// ============================================================================
__device__ __forceinline__ uint32_t smem_u32(const void* p) {
    uint32_t a;
    asm("{ .reg .u64 t; cvta.to.shared.u64 t, %1; cvt.u32.u64 %0, t; }" : "=r"(a) : "l"(p));
    return a;
}
__device__ __forceinline__ void mma_bf16(float* d, const uint32_t* a, uint32_t b0, uint32_t b1) {
    asm volatile(
        "mma.sync.aligned.m16n8k16.row.col.f32.bf16.bf16.f32 "
        "{%0,%1,%2,%3}, {%4,%5,%6,%7}, {%8,%9}, {%0,%1,%2,%3};"
        : "+f"(d[0]), "+f"(d[1]), "+f"(d[2]), "+f"(d[3])
        : "r"(a[0]), "r"(a[1]), "r"(a[2]), "r"(a[3]), "r"(b0), "r"(b1));
}
__device__ __forceinline__ void ldm4(uint32_t* r, uint32_t a) {
    asm volatile("ldmatrix.sync.aligned.m8n8.x4.shared.b16 {%0,%1,%2,%3}, [%4];"
                 : "=r"(r[0]), "=r"(r[1]), "=r"(r[2]), "=r"(r[3]) : "r"(a));
}
__device__ __forceinline__ void ldm4t(uint32_t* r, uint32_t a) {
    asm volatile("ldmatrix.sync.aligned.m8n8.x4.trans.shared.b16 {%0,%1,%2,%3}, [%4];"
                 : "=r"(r[0]), "=r"(r[1]), "=r"(r[2]), "=r"(r[3]) : "r"(a));
}
__device__ __forceinline__ void cp16(uint32_t dst, const void* src) {
    asm volatile("cp.async.cg.shared.global [%0], [%1], 16;" :: "r"(dst), "l"(src));
}
#define CP_COMMIT() asm volatile("cp.async.commit_group;" ::: "memory")
#define CP_WAIT0()  asm volatile("cp.async.wait_group 0;" ::: "memory")

__device__ __forceinline__ uint32_t pk(float a, float b) {
    __nv_bfloat162 t = __floats2bfloat162_rn(a, b);
    return *reinterpret_cast<uint32_t*>(&t);
}
__device__ __forceinline__ void splitpk(float a, float b, uint32_t& hh, uint32_t& ll) {
    float ah = __bfloat162float(__float2bfloat16_rn(a));
    float bh = __bfloat162float(__float2bfloat16_rn(b));
    hh = pk(ah, bh);
    ll = pk(a - ah, b - bh);
}

// ============================================================================
// transpose + split: out_[h|l][n][k] = split(in[k][n]), 1024x1024
// ============================================================================
__global__ __launch_bounds__(256) void transpose_split(const float* __restrict__ in,
                                                       bf16* __restrict__ oh,
                                                       bf16* __restrict__ ol) {
    __shared__ float t[32][33];
    int x = blockIdx.x * 32 + threadIdx.x;
    int y0 = blockIdx.y * 32 + threadIdx.y;
#pragma unroll
    for (int i = 0; i < 32; i += 8)
        t[threadIdx.y + i][threadIdx.x] = in[(size_t)(y0 + i) * D_ + x];
    __syncthreads();
    x = blockIdx.y * 32 + threadIdx.x;
    y0 = blockIdx.x * 32 + threadIdx.y;
#pragma unroll
    for (int i = 0; i < 32; i += 8) {
        float v = t[threadIdx.x][threadIdx.y + i];
        bf16 h = __float2bfloat16_rn(v);
        oh[(size_t)(y0 + i) * D_ + x] = h;
        ol[(size_t)(y0 + i) * D_ + x] = __float2bfloat16_rn(v - __bfloat162float(h));
    }
}

// ============================================================================
// split fp32 -> bf16 h/l, vectorized
// ============================================================================
__global__ __launch_bounds__(256) void split2(const float4* __restrict__ in,
                                              uint32_t* __restrict__ oh,
                                              uint32_t* __restrict__ ol, int n4) {
    int i = blockIdx.x * 256 + threadIdx.x;
    if (i >= n4) return;
    float4 v = in[i];
    uint32_t h0, l0, h1, l1;
    splitpk(v.x, v.y, h0, l0);
    splitpk(v.z, v.w, h1, l1);
    oh[i * 2] = h0; oh[i * 2 + 1] = h1;
    ol[i * 2] = l0; ol[i * 2 + 1] = l1;
}

// ============================================================================
// bf16x3 GEMM: C[M,1024] = (A @ Wt^T + bias) * scale
// Block 128x128, BK=32, 8 warps (2m x 4n), 2-stage cp.async, 1 sync/iter.
// ============================================================================
#define GKS 40
#define GTILE (128 * GKS)
#define G_SMEM (2 * 4 * GTILE * 2)  // 81920 bytes

__global__ __launch_bounds__(256) void gemm_bf3(
    const bf16* __restrict__ Ah, const bf16* __restrict__ Al,
    const bf16* __restrict__ Bh, const bf16* __restrict__ Bl,
    const float* __restrict__ bias, float scale,
    float* __restrict__ outF, bf16* __restrict__ outH, bf16* __restrict__ outL)
{
    extern __shared__ bf16 sb[];
    const uint32_t sbase = smem_u32(sb);
    const int tid = threadIdx.x, lane = tid & 31, wid = tid >> 5;
    const int wm = wid & 1, wn = wid >> 1;
    const int row0 = blockIdx.y * 128, col0 = blockIdx.x * 128;

    float d[4][4][4] = {};

    auto load_stage = [&](int s, int kt) {
        const bf16* srcs[4] = {Ah, Al, Bh, Bl};
        const int rb[4] = {row0, row0, col0, col0};
#pragma unroll
        for (int bi = 0; bi < 4; ++bi) {
#pragma unroll
            for (int it = 0; it < 2; ++it) {
                int ch = tid + it * 256;
                int r = ch >> 2, c8 = ch & 3;
                const bf16* g = srcs[bi] + (size_t)(rb[bi] + r) * D_ + kt * 32 + c8 * 8;
                cp16(sbase + ((s * 4 + bi) * GTILE + r * GKS + c8 * 8) * 2, g);
            }
        }
    };

    auto compute_stage = [&](int s) {
        const uint32_t aB  = sbase + (s * 4 + 0) * GTILE * 2;
        const uint32_t alB = sbase + (s * 4 + 1) * GTILE * 2;
        const uint32_t bB  = sbase + (s * 4 + 2) * GTILE * 2;
        const uint32_t blB = sbase + (s * 4 + 3) * GTILE * 2;
        const int l15 = lane & 15, l7 = lane & 7;
        const int aro = (lane & 16) ? 8 : 0;
        const int bko = (lane & 8) ? 8 : 0;
        const int bro = (lane & 16) ? 8 : 0;
#pragma unroll
        for (int kh2 = 0; kh2 < 2; ++kh2) {
            uint32_t ah[4][4], al[4][4], bh[2][4], bl[2][4];
#pragma unroll
            for (int i = 0; i < 4; ++i) {
                uint32_t off = (uint32_t)((wm * 64 + i * 16 + l15) * GKS + kh2 * 16 + aro) * 2;
                ldm4(ah[i], aB + off);
                ldm4(al[i], alB + off);
            }
#pragma unroll
            for (int nb = 0; nb < 2; ++nb) {
                uint32_t off = (uint32_t)((wn * 32 + nb * 16 + l7 + bro) * GKS + kh2 * 16 + bko) * 2;
                ldm4(bh[nb], bB + off);
                ldm4(bl[nb], blB + off);
            }
#pragma unroll
            for (int i = 0; i < 4; ++i)
#pragma unroll
                for (int j = 0; j < 4; ++j) {
                    const int nb = j >> 1, hf = (j & 1) * 2;
                    mma_bf16(d[i][j], ah[i], bh[nb][hf], bh[nb][hf + 1]);
                    mma_bf16(d[i][j], ah[i], bl[nb][hf], bl[nb][hf + 1]);
                    mma_bf16(d[i][j], al[i], bh[nb][hf], bh[nb][hf + 1]);
                }
        }
    };

    load_stage(0, 0); CP_COMMIT();
    for (int kt = 0; kt < 32; ++kt) {
        CP_WAIT0();                 // stage kt landed
        __syncthreads();            // everyone done with stage kt^1 (prev compute)
        if (kt + 1 < 32) { load_stage((kt + 1) & 1, kt + 1); CP_COMMIT(); }
        compute_stage(kt & 1);
    }

    // Epilogue
    const int lr = lane >> 2, lc = lane & 3;
#pragma unroll
    for (int i = 0; i < 4; ++i) {
        const int r0g = row0 + wm * 64 + i * 16 + lr;
#pragma unroll
        for (int j = 0; j < 4; ++j) {
            const int cg = col0 + wn * 32 + j * 8 + lc * 2;
            const float2 bb = *(const float2*)&bias[cg];
            const float v0 = (d[i][j][0] + bb.x) * scale;
            const float v1 = (d[i][j][1] + bb.y) * scale;
            const float v2 = (d[i][j][2] + bb.x) * scale;
            const float v3 = (d[i][j][3] + bb.y) * scale;
            if (outF) {
                *(float2*)&outF[(size_t)r0g * D_ + cg] = make_float2(v0, v1);
                *(float2*)&outF[(size_t)(r0g + 8) * D_ + cg] = make_float2(v2, v3);
            } else {
                uint32_t hh, ll;
                splitpk(v0, v1, hh, ll);
                *(uint32_t*)(outH + (size_t)r0g * D_ + cg) = hh;
                *(uint32_t*)(outL + (size_t)r0g * D_ + cg) = ll;
                splitpk(v2, v3, hh, ll);
                *(uint32_t*)(outH + (size_t)(r0g + 8) * D_ + cg) = hh;
                *(uint32_t*)(outL + (size_t)(r0g + 8) * D_ + cg) = ll;
            }
        }
    }
}

// ============================================================================
// Flash attention, bf16x3 mma.sync. Block = 128 q-rows x head x batch,
// 256 threads (8 warps x 16 q-rows), 32 kv-tiles of 64, 2-stage cp.async.
// Q pre-scaled by 1/8 at projection time.
// ============================================================================
#define AST 72
#define ABUF (64 * AST)          // bf16 elems per 64-row buffer
#define A_SMEM (8 * ABUF * 2)    // 73728 bytes: 2 stages x (Kh,Kl,Vh,Vl)

__global__ __launch_bounds__(256) void attn_bf3(
    const bf16* __restrict__ Qh, const bf16* __restrict__ Ql,
    const bf16* __restrict__ Kh, const bf16* __restrict__ Kl,
    const bf16* __restrict__ Vh, const bf16* __restrict__ Vl,
    bf16* __restrict__ Oh, bf16* __restrict__ Ol)
{
    extern __shared__ bf16 sa_[];
    const uint32_t sbase = smem_u32(sa_);
    const int tid = threadIdx.x, lane = tid & 31, wq = tid >> 5;
    const int q0 = blockIdx.x * 128, hd = blockIdx.y, bb = blockIdx.z;
    const size_t gbase = ((size_t)bb * T_) * D_ + (size_t)hd * 64;

    // ---- Load Q tile (128 rows, h+l) into stage-0 area, extract fragments ----
    {
        const bf16* s0p = Qh + gbase + (size_t)q0 * D_;
        const bf16* s1p = Ql + gbase + (size_t)q0 * D_;
#pragma unroll
        for (int it = 0; it < 4; ++it) {
            const int ch = tid + it * 256;          // 0..1023
            const int r = ch >> 3, c8 = ch & 7;
            cp16(sbase + (r * AST + c8 * 8) * 2, s0p + (size_t)r * D_ + c8 * 8);
            cp16(sbase + (2 * ABUF + r * AST + c8 * 8) * 2, s1p + (size_t)r * D_ + c8 * 8);
        }
        CP_COMMIT(); CP_WAIT0();
        __syncthreads();
    }
    uint32_t qh[4][4], ql[4][4];
    {
        const int l15 = lane & 15;
        const int ao = (lane & 16) ? 8 : 0;
#pragma unroll
        for (int ka = 0; ka < 4; ++ka) {
            const uint32_t off = (uint32_t)((wq * 16 + l15) * AST + ka * 16 + ao) * 2;
            ldm4(qh[ka], sbase + off);
            ldm4(ql[ka], sbase + 2 * ABUF * 2 + off);
        }
    }
    __syncthreads();

    float O[8][4] = {};
    float m0 = -1e30f, m1 = -1e30f, l0 = 0.f, l1 = 0.f;

    auto issue_kv = [&](int s, int t) {
        const bf16* srcs[4] = {Kh, Kl, Vh, Vl};
#pragma unroll
        for (int bi = 0; bi < 4; ++bi) {
            const bf16* g0 = srcs[bi] + gbase + (size_t)(t * 64) * D_;
#pragma unroll
            for (int it = 0; it < 2; ++it) {
                const int ch = tid + it * 256;      // 0..511
                const int r = ch >> 3, c8 = ch & 7;
                cp16(sbase + ((s * 4 + bi) * ABUF + r * AST + c8 * 8) * 2,
                     g0 + (size_t)r * D_ + c8 * 8);
            }
        }
        CP_COMMIT();
    };

    issue_kv(0, 0);
    for (int t = 0; t < 32; ++t) {
        CP_WAIT0();                  // stage t landed
        __syncthreads();             // everyone done reading stage t^1
        if (t + 1 < 32) issue_kv((t + 1) & 1, t + 1);
        const uint32_t stB = sbase + (uint32_t)((t & 1) * 4) * ABUF * 2;

        // ---- S = Q K^T (bf16x3) ----
        float S[8][4] = {};
        {
            const int l7 = lane & 7;
            const int bro = (lane & 16) ? 8 : 0;
            const int bko = (lane & 8) ? 8 : 0;
#pragma unroll
            for (int ka = 0; ka < 4; ++ka)
#pragma unroll
                for (int nb = 0; nb < 4; ++nb) {
                    const uint32_t off =
                        (uint32_t)((nb * 16 + l7 + bro) * AST + ka * 16 + bko) * 2;
                    uint32_t kh[4], kl[4];
                    ldm4(kh, stB + off);
                    ldm4(kl, stB + ABUF * 2 + off);
                    mma_bf16(S[2 * nb],     qh[ka], kh[0], kh[1]);
                    mma_bf16(S[2 * nb],     qh[ka], kl[0], kl[1]);
                    mma_bf16(S[2 * nb],     ql[ka], kh[0], kh[1]);
                    mma_bf16(S[2 * nb + 1], qh[ka], kh[2], kh[3]);
                    mma_bf16(S[2 * nb + 1], qh[ka], kl[2], kl[3]);
                    mma_bf16(S[2 * nb + 1], ql[ka], kh[2], kh[3]);
                }
        }

        // ---- Online softmax (register, 4-lane row groups) ----
        float mx0 = -1e30f, mx1 = -1e30f;
#pragma unroll
        for (int j = 0; j < 8; ++j) {
            mx0 = fmaxf(mx0, fmaxf(S[j][0], S[j][1]));
            mx1 = fmaxf(mx1, fmaxf(S[j][2], S[j][3]));
        }
        mx0 = fmaxf(mx0, __shfl_xor_sync(0xffffffffu, mx0, 1));
        mx0 = fmaxf(mx0, __shfl_xor_sync(0xffffffffu, mx0, 2));
        mx1 = fmaxf(mx1, __shfl_xor_sync(0xffffffffu, mx1, 1));
        mx1 = fmaxf(mx1, __shfl_xor_sync(0xffffffffu, mx1, 2));
        const float mn0 = fmaxf(m0, mx0), mn1 = fmaxf(m1, mx1);
        const float c0 = __expf(m0 - mn0), c1 = __expf(m1 - mn1);

        uint32_t ph[4][4], pl[4][4];
        float r0 = 0.f, r1 = 0.f;
#pragma unroll
        for (int j = 0; j < 8; ++j) {
            const float p0 = __expf(S[j][0] - mn0);
            const float p1 = __expf(S[j][1] - mn0);
            const float p2 = __expf(S[j][2] - mn1);
            const float p3 = __expf(S[j][3] - mn1);
            r0 += p0 + p1; r1 += p2 + p3;
            const int tj = j >> 1, o = (j & 1) * 2;
            uint32_t hh, ll;
            splitpk(p0, p1, hh, ll); ph[tj][o] = hh;     pl[tj][o] = ll;
            splitpk(p2, p3, hh, ll); ph[tj][o + 1] = hh; pl[tj][o + 1] = ll;
        }
        r0 += __shfl_xor_sync(0xffffffffu, r0, 1);
        r0 += __shfl_xor_sync(0xffffffffu, r0, 2);
        r1 += __shfl_xor_sync(0xffffffffu, r1, 1);
        r1 += __shfl_xor_sync(0xffffffffu, r1, 2);
        l0 = l0 * c0 + r0; l1 = l1 * c1 + r1;
        m0 = mn0; m1 = mn1;
#pragma unroll
        for (int j = 0; j < 8; ++j) {
            O[j][0] *= c0; O[j][1] *= c0; O[j][2] *= c1; O[j][3] *= c1;
        }

        // ---- O += P V (bf16x3, V via ldmatrix.trans) ----
        {
            const int l15 = lane & 15;
            const int no = (lane & 16) ? 8 : 0;
#pragma unroll
            for (int kt = 0; kt < 4; ++kt)
#pragma unroll
                for (int nb = 0; nb < 4; ++nb) {
                    const uint32_t off =
                        (uint32_t)((kt * 16 + l15) * AST + nb * 16 + no) * 2;
                    uint32_t vh[4], vl[4];
                    ldm4t(vh, stB + 2 * ABUF * 2 + off);
                    ldm4t(vl, stB + 3 * ABUF * 2 + off);
                    mma_bf16(O[2 * nb],     ph[kt], vh[0], vh[1]);
                    mma_bf16(O[2 * nb],     ph[kt], vl[0], vl[1]);
                    mma_bf16(O[2 * nb],     pl[kt], vh[0], vh[1]);
                    mma_bf16(O[2 * nb + 1], ph[kt], vh[2], vh[3]);
                    mma_bf16(O[2 * nb + 1], ph[kt], vl[2], vl[3]);
                    mma_bf16(O[2 * nb + 1], pl[kt], vh[2], vh[3]);
                }
        }
    }

    // ---- Epilogue: normalize, split to bf16 h/l ----
    const int lr = lane >> 2, lc = lane & 3;
    const float inv0 = 1.f / l0, inv1 = 1.f / l1;
    const size_t rA = (size_t)bb * T_ + q0 + wq * 16 + lr;
    const size_t rB = rA + 8;
#pragma unroll
    for (int j = 0; j < 8; ++j) {
        const int cg = hd * 64 + j * 8 + lc * 2;
        uint32_t hh, ll;
        splitpk(O[j][0] * inv0, O[j][1] * inv0, hh, ll);
        *(uint32_t*)(Oh + rA * D_ + cg) = hh;
        *(uint32_t*)(Ol + rA * D_ + cg) = ll;
        splitpk(O[j][2] * inv1, O[j][3] * inv1, hh, ll);
        *(uint32_t*)(Oh + rB * D_ + cg) = hh;
        *(uint32_t*)(Ol + rB * D_ + cg) = ll;
    }
}

// ============================================================================
extern "C" void kernel_launch(void* const* d_in, const int* in_sizes, int n_in,
                              void* d_out, int out_size)
{
    (void)in_sizes; (void)n_in; (void)out_size;
    const float* q   = (const float*)d_in[0];
    const float* k   = (const float*)d_in[1];
    const float* v   = (const float*)d_in[2];
    const float* Wq  = (const float*)d_in[3];
    const float* b_q = (const float*)d_in[4];
    const float* Wk  = (const float*)d_in[5];
    const float* b_k = (const float*)d_in[6];
    const float* Wv  = (const float*)d_in[7];
    const float* b_v = (const float*)d_in[8];
    const float* Wo  = (const float*)d_in[9];
    const float* b_o = (const float*)d_in[10];
    float* out = (float*)d_out;

    bf16 *in6, *qkv, *att, *w8;
    cudaGetSymbolAddress((void**)&in6, g_in6);
    cudaGetSymbolAddress((void**)&qkv, g_qkv);
    cudaGetSymbolAddress((void**)&att, g_att);
    cudaGetSymbolAddress((void**)&w8,  g_w8);

    cudaFuncSetAttribute(gemm_bf3, cudaFuncAttributeMaxDynamicSharedMemorySize, G_SMEM);
    cudaFuncSetAttribute(attn_bf3, cudaFuncAttributeMaxDynamicSharedMemorySize, A_SMEM);

    // Transpose + split weights
    dim3 tgrid(32, 32), tblk(32, 8);
    transpose_split<<<tgrid, tblk>>>(Wq, w8 + 0 * DD_, w8 + 1 * DD_);
    transpose_split<<<tgrid, tblk>>>(Wk, w8 + 2 * DD_, w8 + 3 * DD_);
    transpose_split<<<tgrid, tblk>>>(Wv, w8 + 4 * DD_, w8 + 5 * DD_);
    transpose_split<<<tgrid, tblk>>>(Wo, w8 + 6 * DD_, w8 + 7 * DD_);

    // Split activations
    const int n4 = (int)(MD_ / 4);
    split2<<<n4 / 256, 256>>>((const float4*)q, (uint32_t*)(in6 + 0 * MD_), (uint32_t*)(in6 + 1 * MD_), n4);
    split2<<<n4 / 256, 256>>>((const float4*)k, (uint32_t*)(in6 + 2 * MD_), (uint32_t*)(in6 + 3 * MD_), n4);
    split2<<<n4 / 256, 256>>>((const float4*)v, (uint32_t*)(in6 + 4 * MD_), (uint32_t*)(in6 + 5 * MD_), n4);

    // Projections (Q pre-scaled by 1/sqrt(DH)=0.125)
    dim3 ggrid(D_ / 128, M_ / 128);  // 8 x 64
    gemm_bf3<<<ggrid, 256, G_SMEM>>>(in6 + 0 * MD_, in6 + 1 * MD_, w8 + 0 * DD_, w8 + 1 * DD_,
                                     b_q, 0.125f, nullptr, qkv + 0 * MD_, qkv + 1 * MD_);
    gemm_bf3<<<ggrid, 256, G_SMEM>>>(in6 + 2 * MD_, in6 + 3 * MD_, w8 + 2 * DD_, w8 + 3 * DD_,
                                     b_k, 1.0f, nullptr, qkv + 2 * MD_, qkv + 3 * MD_);
    gemm_bf3<<<ggrid, 256, G_SMEM>>>(in6 + 4 * MD_, in6 + 5 * MD_, w8 + 4 * DD_, w8 + 5 * DD_,
                                     b_v, 1.0f, nullptr, qkv + 4 * MD_, qkv + 5 * MD_);

    // Attention (q-tile 128, 8 warps)
    dim3 agrid(T_ / 128, H_, B_);    // 16 x 16 x 4
    attn_bf3<<<agrid, 256, A_SMEM>>>(qkv + 0 * MD_, qkv + 1 * MD_, qkv + 2 * MD_,
                                     qkv + 3 * MD_, qkv + 4 * MD_, qkv + 5 * MD_,
                                     att + 0 * MD_, att + 1 * MD_);

    // Output projection -> fp32
    gemm_bf3<<<ggrid, 256, G_SMEM>>>(att + 0 * MD_, att + 1 * MD_, w8 + 6 * DD_, w8 + 7 * DD_,
                                     b_o, 1.0f, out, nullptr, nullptr);
}

// round 6
// speedup vs baseline: 8.8303x; 2.2807x over previous
#include <cuda_runtime.h>
#include <cuda_fp16.h>
#include <cstdint>
#include <math.h>

typedef __half half_t;

// Problem constants
#define B_  4
#define T_  2048
#define D_  1024
#define H_  16
#define DH_ 64
#define M_  (B_ * T_)   // 8192
#define DD_ ((size_t)D_ * D_)
#define MD_ ((size_t)M_ * D_)

// Scratch (single fp16 everywhere)
__device__ half_t g_in3[3][MD_];   // q,k,v converted
__device__ half_t g_qkv[3][MD_];   // Q (pre-scaled 1/8), K, V
__device__ half_t g_att[MD_];      // attention output
__device__ half_t g_w4[4][DD_];    // Wq,Wk,Wv,Wo transposed [N][K]

// ============================================================================
// PTX helpers
// ============================================================================
__device__ __forceinline__ uint32_t smem_u32(const void* p) {
    uint32_t a;
    asm("{ .reg .u64 t; cvta.to.shared.u64 t, %1; cvt.u32.u64 %0, t; }" : "=r"(a) : "l"(p));
    return a;
}
__device__ __forceinline__ void mma_f16(float* d, const uint32_t* a, uint32_t b0, uint32_t b1) {
    asm volatile(
        "mma.sync.aligned.m16n8k16.row.col.f32.f16.f16.f32 "
        "{%0,%1,%2,%3}, {%4,%5,%6,%7}, {%8,%9}, {%0,%1,%2,%3};"
        : "+f"(d[0]), "+f"(d[1]), "+f"(d[2]), "+f"(d[3])
        : "r"(a[0]), "r"(a[1]), "r"(a[2]), "r"(a[3]), "r"(b0), "r"(b1));
}
__device__ __forceinline__ void ldm4(uint32_t* r, uint32_t a) {
    asm volatile("ldmatrix.sync.aligned.m8n8.x4.shared.b16 {%0,%1,%2,%3}, [%4];"
                 : "=r"(r[0]), "=r"(r[1]), "=r"(r[2]), "=r"(r[3]) : "r"(a));
}
__device__ __forceinline__ void ldm4t(uint32_t* r, uint32_t a) {
    asm volatile("ldmatrix.sync.aligned.m8n8.x4.trans.shared.b16 {%0,%1,%2,%3}, [%4];"
                 : "=r"(r[0]), "=r"(r[1]), "=r"(r[2]), "=r"(r[3]) : "r"(a));
}
__device__ __forceinline__ void cp16(uint32_t dst, const void* src) {
    asm volatile("cp.async.cg.shared.global [%0], [%1], 16;" :: "r"(dst), "l"(src));
}
#define CP_COMMIT() asm volatile("cp.async.commit_group;" ::: "memory")
#define CP_WAIT0()  asm volatile("cp.async.wait_group 0;" ::: "memory")

__device__ __forceinline__ uint32_t pkh(float a, float b) {
    __half2 t = __floats2half2_rn(a, b);
    return *reinterpret_cast<uint32_t*>(&t);
}

// ============================================================================
// transpose + convert: out[n][k] = fp16(in[k][n]), 1024x1024
// ============================================================================
__global__ __launch_bounds__(256) void transpose_cvt(const float* __restrict__ in,
                                                     half_t* __restrict__ o) {
    __shared__ float t[32][33];
    int x = blockIdx.x * 32 + threadIdx.x;
    int y0 = blockIdx.y * 32 + threadIdx.y;
#pragma unroll
    for (int i = 0; i < 32; i += 8)
        t[threadIdx.y + i][threadIdx.x] = in[(size_t)(y0 + i) * D_ + x];
    __syncthreads();
    x = blockIdx.y * 32 + threadIdx.x;
    y0 = blockIdx.x * 32 + threadIdx.y;
#pragma unroll
    for (int i = 0; i < 32; i += 8)
        o[(size_t)(y0 + i) * D_ + x] = __float2half_rn(t[threadIdx.x][threadIdx.y + i]);
}

// ============================================================================
// convert fp32 -> fp16, vectorized
// ============================================================================
__global__ __launch_bounds__(256) void tohalf(const float4* __restrict__ in,
                                              uint2* __restrict__ out, int n4) {
    int i = blockIdx.x * 256 + threadIdx.x;
    if (i >= n4) return;
    float4 v = in[i];
    uint2 o;
    o.x = pkh(v.x, v.y);
    o.y = pkh(v.z, v.w);
    out[i] = o;
}

// ============================================================================
// fp16 GEMM: C[M,1024] = (A @ Wt^T + bias) * scale
// Block 128x128, BK=32, 8 warps (2m x 4n), 2-stage cp.async, 1 sync/iter.
// ============================================================================
#define GKS 40
#define GTILE (128 * GKS)            // halves per tile buffer
#define G_SMEM (2 * 2 * GTILE * 2)   // 40960 bytes

__global__ __launch_bounds__(256) void gemm_f16(
    const half_t* __restrict__ A, const half_t* __restrict__ Bt,
    const float* __restrict__ bias, float scale,
    float* __restrict__ outF, half_t* __restrict__ outH)
{
    extern __shared__ half_t sb[];
    const uint32_t sbase = smem_u32(sb);
    const int tid = threadIdx.x, lane = tid & 31, wid = tid >> 5;
    const int wm = wid & 1, wn = wid >> 1;
    const int row0 = blockIdx.y * 128, col0 = blockIdx.x * 128;

    float d[4][4][4] = {};

    auto load_stage = [&](int s, int kt) {
        const half_t* srcs[2] = {A, Bt};
        const int rb[2] = {row0, col0};
#pragma unroll
        for (int bi = 0; bi < 2; ++bi) {
#pragma unroll
            for (int it = 0; it < 2; ++it) {
                int ch = tid + it * 256;              // 0..511
                int r = ch >> 2, c8 = ch & 3;
                const half_t* g = srcs[bi] + (size_t)(rb[bi] + r) * D_ + kt * 32 + c8 * 8;
                cp16(sbase + ((s * 2 + bi) * GTILE + r * GKS + c8 * 8) * 2, g);
            }
        }
    };

    auto compute_stage = [&](int s) {
        const uint32_t aB = sbase + (s * 2 + 0) * GTILE * 2;
        const uint32_t bB = sbase + (s * 2 + 1) * GTILE * 2;
        const int l15 = lane & 15, l7 = lane & 7;
        const int aro = (lane & 16) ? 8 : 0;
        const int bko = (lane & 8) ? 8 : 0;
        const int bro = (lane & 16) ? 8 : 0;
#pragma unroll
        for (int kh2 = 0; kh2 < 2; ++kh2) {
            uint32_t af[4][4], bf[2][4];
#pragma unroll
            for (int i = 0; i < 4; ++i) {
                uint32_t off = (uint32_t)((wm * 64 + i * 16 + l15) * GKS + kh2 * 16 + aro) * 2;
                ldm4(af[i], aB + off);
            }
#pragma unroll
            for (int nb = 0; nb < 2; ++nb) {
                uint32_t off = (uint32_t)((wn * 32 + nb * 16 + l7 + bro) * GKS + kh2 * 16 + bko) * 2;
                ldm4(bf[nb], bB + off);
            }
#pragma unroll
            for (int i = 0; i < 4; ++i)
#pragma unroll
                for (int j = 0; j < 4; ++j) {
                    const int nb = j >> 1, hf = (j & 1) * 2;
                    mma_f16(d[i][j], af[i], bf[nb][hf], bf[nb][hf + 1]);
                }
        }
    };

    load_stage(0, 0); CP_COMMIT();
    for (int kt = 0; kt < 32; ++kt) {
        CP_WAIT0();
        __syncthreads();
        if (kt + 1 < 32) { load_stage((kt + 1) & 1, kt + 1); CP_COMMIT(); }
        compute_stage(kt & 1);
    }

    // Epilogue
    const int lr = lane >> 2, lc = lane & 3;
#pragma unroll
    for (int i = 0; i < 4; ++i) {
        const int r0g = row0 + wm * 64 + i * 16 + lr;
#pragma unroll
        for (int j = 0; j < 4; ++j) {
            const int cg = col0 + wn * 32 + j * 8 + lc * 2;
            const float2 bb = *(const float2*)&bias[cg];
            const float v0 = (d[i][j][0] + bb.x) * scale;
            const float v1 = (d[i][j][1] + bb.y) * scale;
            const float v2 = (d[i][j][2] + bb.x) * scale;
            const float v3 = (d[i][j][3] + bb.y) * scale;
            if (outF) {
                *(float2*)&outF[(size_t)r0g * D_ + cg] = make_float2(v0, v1);
                *(float2*)&outF[(size_t)(r0g + 8) * D_ + cg] = make_float2(v2, v3);
            } else {
                *(uint32_t*)(outH + (size_t)r0g * D_ + cg) = pkh(v0, v1);
                *(uint32_t*)(outH + (size_t)(r0g + 8) * D_ + cg) = pkh(v2, v3);
            }
        }
    }
}

// ============================================================================
// Flash attention, fp16 mma.sync. Block = 128 q-rows x head x batch,
// 256 threads (8 warps x 16 q-rows), 32 kv-tiles of 64, 2-stage cp.async.
// Q pre-scaled by 1/8 at projection time. fp32 softmax/accumulators.
// ============================================================================
#define AST 72
#define ABUF (64 * AST)          // halves per 64-row buffer
#define A_SMEM (4 * ABUF * 2)    // 36864 bytes: 2 stages x (K, V)

__global__ __launch_bounds__(256) void attn_f16(
    const half_t* __restrict__ Qg, const half_t* __restrict__ Kg,
    const half_t* __restrict__ Vg, half_t* __restrict__ Og)
{
    extern __shared__ half_t sa_[];
    const uint32_t sbase = smem_u32(sa_);
    const int tid = threadIdx.x, lane = tid & 31, wq = tid >> 5;
    const int q0 = blockIdx.x * 128, hd = blockIdx.y, bb = blockIdx.z;
    const size_t gbase = ((size_t)bb * T_) * D_ + (size_t)hd * 64;

    // ---- Load Q tile (128 rows), extract fragments ----
    {
        const half_t* qp = Qg + gbase + (size_t)q0 * D_;
#pragma unroll
        for (int it = 0; it < 4; ++it) {
            const int ch = tid + it * 256;          // 0..1023
            const int r = ch >> 3, c8 = ch & 7;
            cp16(sbase + (r * AST + c8 * 8) * 2, qp + (size_t)r * D_ + c8 * 8);
        }
        CP_COMMIT(); CP_WAIT0();
        __syncthreads();
    }
    uint32_t qf[4][4];
    {
        const int l15 = lane & 15;
        const int ao = (lane & 16) ? 8 : 0;
#pragma unroll
        for (int ka = 0; ka < 4; ++ka) {
            const uint32_t off = (uint32_t)((wq * 16 + l15) * AST + ka * 16 + ao) * 2;
            ldm4(qf[ka], sbase + off);
        }
    }
    __syncthreads();

    float O[8][4] = {};
    float m0 = -1e30f, m1 = -1e30f, l0 = 0.f, l1 = 0.f;

    auto issue_kv = [&](int s, int t) {
        const half_t* srcs[2] = {Kg, Vg};
#pragma unroll
        for (int bi = 0; bi < 2; ++bi) {
            const half_t* g0 = srcs[bi] + gbase + (size_t)(t * 64) * D_;
#pragma unroll
            for (int it = 0; it < 2; ++it) {
                const int ch = tid + it * 256;      // 0..511
                const int r = ch >> 3, c8 = ch & 7;
                cp16(sbase + ((s * 2 + bi) * ABUF + r * AST + c8 * 8) * 2,
                     g0 + (size_t)r * D_ + c8 * 8);
            }
        }
        CP_COMMIT();
    };

    issue_kv(0, 0);
    for (int t = 0; t < 32; ++t) {
        CP_WAIT0();
        __syncthreads();
        if (t + 1 < 32) issue_kv((t + 1) & 1, t + 1);
        const uint32_t stB = sbase + (uint32_t)((t & 1) * 2) * ABUF * 2;

        // ---- S = Q K^T ----
        float S[8][4] = {};
        {
            const int l7 = lane & 7;
            const int bro = (lane & 16) ? 8 : 0;
            const int bko = (lane & 8) ? 8 : 0;
#pragma unroll
            for (int ka = 0; ka < 4; ++ka)
#pragma unroll
                for (int nb = 0; nb < 4; ++nb) {
                    const uint32_t off =
                        (uint32_t)((nb * 16 + l7 + bro) * AST + ka * 16 + bko) * 2;
                    uint32_t kf[4];
                    ldm4(kf, stB + off);
                    mma_f16(S[2 * nb],     qf[ka], kf[0], kf[1]);
                    mma_f16(S[2 * nb + 1], qf[ka], kf[2], kf[3]);
                }
        }

        // ---- Online softmax (register, 4-lane row groups) ----
        float mx0 = -1e30f, mx1 = -1e30f;
#pragma unroll
        for (int j = 0; j < 8; ++j) {
            mx0 = fmaxf(mx0, fmaxf(S[j][0], S[j][1]));
            mx1 = fmaxf(mx1, fmaxf(S[j][2], S[j][3]));
        }
        mx0 = fmaxf(mx0, __shfl_xor_sync(0xffffffffu, mx0, 1));
        mx0 = fmaxf(mx0, __shfl_xor_sync(0xffffffffu, mx0, 2));
        mx1 = fmaxf(mx1, __shfl_xor_sync(0xffffffffu, mx1, 1));
        mx1 = fmaxf(mx1, __shfl_xor_sync(0xffffffffu, mx1, 2));
        const float mn0 = fmaxf(m0, mx0), mn1 = fmaxf(m1, mx1);
        const float c0 = __expf(m0 - mn0), c1 = __expf(m1 - mn1);

        uint32_t pf[4][4];
        float r0 = 0.f, r1 = 0.f;
#pragma unroll
        for (int j = 0; j < 8; ++j) {
            const float p0 = __expf(S[j][0] - mn0);
            const float p1 = __expf(S[j][1] - mn0);
            const float p2 = __expf(S[j][2] - mn1);
            const float p3 = __expf(S[j][3] - mn1);
            r0 += p0 + p1; r1 += p2 + p3;
            const int tj = j >> 1, o = (j & 1) * 2;
            pf[tj][o]     = pkh(p0, p1);
            pf[tj][o + 1] = pkh(p2, p3);
        }
        r0 += __shfl_xor_sync(0xffffffffu, r0, 1);
        r0 += __shfl_xor_sync(0xffffffffu, r0, 2);
        r1 += __shfl_xor_sync(0xffffffffu, r1, 1);
        r1 += __shfl_xor_sync(0xffffffffu, r1, 2);
        l0 = l0 * c0 + r0; l1 = l1 * c1 + r1;
        m0 = mn0; m1 = mn1;
#pragma unroll
        for (int j = 0; j < 8; ++j) {
            O[j][0] *= c0; O[j][1] *= c0; O[j][2] *= c1; O[j][3] *= c1;
        }

        // ---- O += P V (V via ldmatrix.trans) ----
        {
            const int l15 = lane & 15;
            const int no = (lane & 16) ? 8 : 0;
#pragma unroll
            for (int kt = 0; kt < 4; ++kt)
#pragma unroll
                for (int nb = 0; nb < 4; ++nb) {
                    const uint32_t off =
                        (uint32_t)((kt * 16 + l15) * AST + nb * 16 + no) * 2;
                    uint32_t vf[4];
                    ldm4t(vf, stB + ABUF * 2 + off);
                    mma_f16(O[2 * nb],     pf[kt], vf[0], vf[1]);
                    mma_f16(O[2 * nb + 1], pf[kt], vf[2], vf[3]);
                }
        }
    }

    // ---- Epilogue: normalize, convert to fp16 ----
    const int lr = lane >> 2, lc = lane & 3;
    const float inv0 = 1.f / l0, inv1 = 1.f / l1;
    const size_t rA = (size_t)bb * T_ + q0 + wq * 16 + lr;
    const size_t rB = rA + 8;
#pragma unroll
    for (int j = 0; j < 8; ++j) {
        const int cg = hd * 64 + j * 8 + lc * 2;
        *(uint32_t*)(Og + rA * D_ + cg) = pkh(O[j][0] * inv0, O[j][1] * inv0);
        *(uint32_t*)(Og + rB * D_ + cg) = pkh(O[j][2] * inv1, O[j][3] * inv1);
    }
}

// ============================================================================
extern "C" void kernel_launch(void* const* d_in, const int* in_sizes, int n_in,
                              void* d_out, int out_size)
{
    (void)in_sizes; (void)n_in; (void)out_size;
    const float* q   = (const float*)d_in[0];
    const float* k   = (const float*)d_in[1];
    const float* v   = (const float*)d_in[2];
    const float* Wq  = (const float*)d_in[3];
    const float* b_q = (const float*)d_in[4];
    const float* Wk  = (const float*)d_in[5];
    const float* b_k = (const float*)d_in[6];
    const float* Wv  = (const float*)d_in[7];
    const float* b_v = (const float*)d_in[8];
    const float* Wo  = (const float*)d_in[9];
    const float* b_o = (const float*)d_in[10];
    float* out = (float*)d_out;

    half_t *in3, *qkv, *att, *w4;
    cudaGetSymbolAddress((void**)&in3, g_in3);
    cudaGetSymbolAddress((void**)&qkv, g_qkv);
    cudaGetSymbolAddress((void**)&att, g_att);
    cudaGetSymbolAddress((void**)&w4,  g_w4);

    cudaFuncSetAttribute(gemm_f16, cudaFuncAttributeMaxDynamicSharedMemorySize, G_SMEM);
    cudaFuncSetAttribute(attn_f16, cudaFuncAttributeMaxDynamicSharedMemorySize, A_SMEM);

    // Transpose + convert weights
    dim3 tgrid(32, 32), tblk(32, 8);
    transpose_cvt<<<tgrid, tblk>>>(Wq, w4 + 0 * DD_);
    transpose_cvt<<<tgrid, tblk>>>(Wk, w4 + 1 * DD_);
    transpose_cvt<<<tgrid, tblk>>>(Wv, w4 + 2 * DD_);
    transpose_cvt<<<tgrid, tblk>>>(Wo, w4 + 3 * DD_);

    // Convert activations
    const int n4 = (int)(MD_ / 4);
    tohalf<<<n4 / 256, 256>>>((const float4*)q, (uint2*)(in3 + 0 * MD_), n4);
    tohalf<<<n4 / 256, 256>>>((const float4*)k, (uint2*)(in3 + 1 * MD_), n4);
    tohalf<<<n4 / 256, 256>>>((const float4*)v, (uint2*)(in3 + 2 * MD_), n4);

    // Projections (Q pre-scaled by 1/sqrt(DH)=0.125)
    dim3 ggrid(D_ / 128, M_ / 128);  // 8 x 64
    gemm_f16<<<ggrid, 256, G_SMEM>>>(in3 + 0 * MD_, w4 + 0 * DD_, b_q, 0.125f,
                                     nullptr, qkv + 0 * MD_);
    gemm_f16<<<ggrid, 256, G_SMEM>>>(in3 + 1 * MD_, w4 + 1 * DD_, b_k, 1.0f,
                                     nullptr, qkv + 1 * MD_);
    gemm_f16<<<ggrid, 256, G_SMEM>>>(in3 + 2 * MD_, w4 + 2 * DD_, b_v, 1.0f,
                                     nullptr, qkv + 2 * MD_);

    // Attention (q-tile 128, 8 warps)
    dim3 agrid(T_ / 128, H_, B_);    // 16 x 16 x 4
    attn_f16<<<agrid, 256, A_SMEM>>>(qkv + 0 * MD_, qkv + 1 * MD_, qkv + 2 * MD_, att);

    // Output projection -> fp32
    gemm_f16<<<ggrid, 256, G_SMEM>>>(att, w4 + 3 * DD_, b_o, 1.0f, out, nullptr);
}

// round 7
// speedup vs baseline: 10.9567x; 1.2408x over previous
#include <cuda_runtime.h>
#include <cuda_fp16.h>
#include <cstdint>
#include <math.h>

typedef __half half_t;

// Problem constants
#define B_  4
#define T_  2048
#define D_  1024
#define H_  16
#define DH_ 64
#define M_  (B_ * T_)   // 8192
#define DD_ ((size_t)D_ * D_)
#define MD_ ((size_t)M_ * D_)

// Q prescale: 1/sqrt(64) * log2(e)  (softmax done in 2^x domain)
#define QSCALE 0.18033688011110932f

// Scratch
__device__ half_t g_in3[3][MD_];   // q,k,v converted
__device__ half_t g_qkv[3][MD_];   // Q (pre-scaled), K, V
__device__ half_t g_att[MD_];      // attention output
__device__ half_t g_w4[4][DD_];    // Wq,Wk,Wv,Wo transposed [N][K]

// ============================================================================
// PTX helpers
// ============================================================================
__device__ __forceinline__ uint32_t smem_u32(const void* p) {
    uint32_t a;
    asm("{ .reg .u64 t; cvta.to.shared.u64 t, %1; cvt.u32.u64 %0, t; }" : "=r"(a) : "l"(p));
    return a;
}
__device__ __forceinline__ void mma_f16(float* d, const uint32_t* a, uint32_t b0, uint32_t b1) {
    asm volatile(
        "mma.sync.aligned.m16n8k16.row.col.f32.f16.f16.f32 "
        "{%0,%1,%2,%3}, {%4,%5,%6,%7}, {%8,%9}, {%0,%1,%2,%3};"
        : "+f"(d[0]), "+f"(d[1]), "+f"(d[2]), "+f"(d[3])
        : "r"(a[0]), "r"(a[1]), "r"(a[2]), "r"(a[3]), "r"(b0), "r"(b1));
}
__device__ __forceinline__ void ldm4(uint32_t* r, uint32_t a) {
    asm volatile("ldmatrix.sync.aligned.m8n8.x4.shared.b16 {%0,%1,%2,%3}, [%4];"
                 : "=r"(r[0]), "=r"(r[1]), "=r"(r[2]), "=r"(r[3]) : "r"(a));
}
__device__ __forceinline__ void ldm4t(uint32_t* r, uint32_t a) {
    asm volatile("ldmatrix.sync.aligned.m8n8.x4.trans.shared.b16 {%0,%1,%2,%3}, [%4];"
                 : "=r"(r[0]), "=r"(r[1]), "=r"(r[2]), "=r"(r[3]) : "r"(a));
}
__device__ __forceinline__ void cp16(uint32_t dst, const void* src) {
    asm volatile("cp.async.cg.shared.global [%0], [%1], 16;" :: "r"(dst), "l"(src));
}
#define CP_COMMIT() asm volatile("cp.async.commit_group;" ::: "memory")
#define CP_WAIT0()  asm volatile("cp.async.wait_group 0;" ::: "memory")

__device__ __forceinline__ uint32_t pkh(float a, float b) {
    __half2 t = __floats2half2_rn(a, b);
    return *reinterpret_cast<uint32_t*>(&t);
}
__device__ __forceinline__ uint32_t ex2_h2(uint32_t x) {
    uint32_t r;
    asm("ex2.approx.f16x2 %0, %1;" : "=r"(r) : "r"(x));
    return r;
}
__device__ __forceinline__ float ex2_f(float x) {
    float r;
    asm("ex2.approx.f32 %0, %1;" : "=f"(r) : "f"(x));
    return r;
}

// ============================================================================
// transpose + convert all 4 weights (grid.z selects)
// ============================================================================
__global__ __launch_bounds__(256) void transpose_cvt4(
    const float* __restrict__ W0, const float* __restrict__ W1,
    const float* __restrict__ W2, const float* __restrict__ W3,
    half_t* __restrict__ o4)
{
    __shared__ float t[32][33];
    const float* in = (blockIdx.z == 0) ? W0 : (blockIdx.z == 1) ? W1
                     : (blockIdx.z == 2) ? W2 : W3;
    half_t* o = o4 + (size_t)blockIdx.z * DD_;
    int x = blockIdx.x * 32 + threadIdx.x;
    int y0 = blockIdx.y * 32 + threadIdx.y;
#pragma unroll
    for (int i = 0; i < 32; i += 8)
        t[threadIdx.y + i][threadIdx.x] = in[(size_t)(y0 + i) * D_ + x];
    __syncthreads();
    x = blockIdx.y * 32 + threadIdx.x;
    y0 = blockIdx.x * 32 + threadIdx.y;
#pragma unroll
    for (int i = 0; i < 32; i += 8)
        o[(size_t)(y0 + i) * D_ + x] = __float2half_rn(t[threadIdx.x][threadIdx.y + i]);
}

// ============================================================================
// convert q,k,v fp32 -> fp16 in one launch (grid.y selects)
// ============================================================================
__global__ __launch_bounds__(256) void tohalf3(
    const float4* __restrict__ q, const float4* __restrict__ k,
    const float4* __restrict__ v, uint2* __restrict__ out3, int n4)
{
    int i = blockIdx.x * 256 + threadIdx.x;
    if (i >= n4) return;
    const float4* in = (blockIdx.y == 0) ? q : (blockIdx.y == 1) ? k : v;
    uint2* out = out3 + (size_t)blockIdx.y * (MD_ / 4) + i;
    float4 vv = in[i];
    uint2 o;
    o.x = pkh(vv.x, vv.y);
    o.y = pkh(vv.z, vv.w);
    *out = o;
}

// ============================================================================
// fp16 GEMM core: C[128,128 tile] = (A @ Wt^T + bias) * scale
// BK=64, 8 warps (2m x 4n), 2-stage cp.async, 1 sync per k-tile.
// ============================================================================
#define GKS 72                       // smem k-stride (halves)
#define GTILE (128 * GKS)            // halves per tile buffer
#define G_SMEM (2 * 2 * GTILE * 2)   // 73728 bytes

__device__ __forceinline__ void gemm_core(
    const half_t* __restrict__ A, const half_t* __restrict__ Bt,
    const float* __restrict__ bias, float scale,
    float* __restrict__ outF, half_t* __restrict__ outH, half_t* sb)
{
    const uint32_t sbase = smem_u32(sb);
    const int tid = threadIdx.x, lane = tid & 31, wid = tid >> 5;
    const int wm = wid & 1, wn = wid >> 1;
    const int row0 = blockIdx.y * 128, col0 = blockIdx.x * 128;

    float d[4][4][4] = {};

    auto load_stage = [&](int s, int kt) {
        const half_t* srcs[2] = {A, Bt};
        const int rb[2] = {row0, col0};
#pragma unroll
        for (int bi = 0; bi < 2; ++bi) {
#pragma unroll
            for (int it = 0; it < 4; ++it) {
                int ch = tid + it * 256;              // 0..1023
                int r = ch >> 3, c8 = ch & 7;
                const half_t* g = srcs[bi] + (size_t)(rb[bi] + r) * D_ + kt * 64 + c8 * 8;
                cp16(sbase + ((s * 2 + bi) * GTILE + r * GKS + c8 * 8) * 2, g);
            }
        }
    };

    auto compute_stage = [&](int s) {
        const uint32_t aB = sbase + (s * 2 + 0) * GTILE * 2;
        const uint32_t bB = sbase + (s * 2 + 1) * GTILE * 2;
        const int l15 = lane & 15, l7 = lane & 7;
        const int aro = (lane & 16) ? 8 : 0;
        const int bko = (lane & 8) ? 8 : 0;
        const int bro = (lane & 16) ? 8 : 0;
#pragma unroll
        for (int kh2 = 0; kh2 < 4; ++kh2) {
            uint32_t af[4][4], bf[2][4];
#pragma unroll
            for (int i = 0; i < 4; ++i) {
                uint32_t off = (uint32_t)((wm * 64 + i * 16 + l15) * GKS + kh2 * 16 + aro) * 2;
                ldm4(af[i], aB + off);
            }
#pragma unroll
            for (int nb = 0; nb < 2; ++nb) {
                uint32_t off = (uint32_t)((wn * 32 + nb * 16 + l7 + bro) * GKS + kh2 * 16 + bko) * 2;
                ldm4(bf[nb], bB + off);
            }
#pragma unroll
            for (int i = 0; i < 4; ++i)
#pragma unroll
                for (int j = 0; j < 4; ++j) {
                    const int nb = j >> 1, hf = (j & 1) * 2;
                    mma_f16(d[i][j], af[i], bf[nb][hf], bf[nb][hf + 1]);
                }
        }
    };

    load_stage(0, 0); CP_COMMIT();
    for (int kt = 0; kt < 16; ++kt) {
        CP_WAIT0();
        __syncthreads();
        if (kt + 1 < 16) { load_stage((kt + 1) & 1, kt + 1); CP_COMMIT(); }
        compute_stage(kt & 1);
    }

    // Epilogue
    const int lr = lane >> 2, lc = lane & 3;
#pragma unroll
    for (int i = 0; i < 4; ++i) {
        const int r0g = row0 + wm * 64 + i * 16 + lr;
#pragma unroll
        for (int j = 0; j < 4; ++j) {
            const int cg = col0 + wn * 32 + j * 8 + lc * 2;
            const float2 bb = *(const float2*)&bias[cg];
            const float v0 = (d[i][j][0] + bb.x) * scale;
            const float v1 = (d[i][j][1] + bb.y) * scale;
            const float v2 = (d[i][j][2] + bb.x) * scale;
            const float v3 = (d[i][j][3] + bb.y) * scale;
            if (outF) {
                *(float2*)&outF[(size_t)r0g * D_ + cg] = make_float2(v0, v1);
                *(float2*)&outF[(size_t)(r0g + 8) * D_ + cg] = make_float2(v2, v3);
            } else {
                *(uint32_t*)(outH + (size_t)r0g * D_ + cg) = pkh(v0, v1);
                *(uint32_t*)(outH + (size_t)(r0g + 8) * D_ + cg) = pkh(v2, v3);
            }
        }
    }
}

// QKV projections in one launch (blockIdx.z selects input/weight/output)
__global__ __launch_bounds__(256) void gemm_qkv(
    const half_t* __restrict__ in3, const half_t* __restrict__ w4,
    const float* __restrict__ b_q, const float* __restrict__ b_k,
    const float* __restrict__ b_v, half_t* __restrict__ qkv)
{
    extern __shared__ half_t sb[];
    const int z = blockIdx.z;
    const float* bias = (z == 0) ? b_q : (z == 1) ? b_k : b_v;
    const float scale = (z == 0) ? QSCALE : 1.0f;
    gemm_core(in3 + (size_t)z * MD_, w4 + (size_t)z * DD_, bias, scale,
              nullptr, qkv + (size_t)z * MD_, sb);
}

// Output projection -> fp32
__global__ __launch_bounds__(256) void gemm_out(
    const half_t* __restrict__ att, const half_t* __restrict__ Wo,
    const float* __restrict__ b_o, float* __restrict__ out)
{
    extern __shared__ half_t sb[];
    gemm_core(att, Wo, b_o, 1.0f, out, nullptr, sb);
}

// ============================================================================
// Flash attention, fp16 mma.sync, log2-domain softmax via ex2.f16x2,
// row-sum via ones-column mma. Block = 128 q-rows x head x batch, 256 threads.
// KV staged 128 rows (two 64-row sub-passes), 2-stage cp.async, 1 sync/stage.
// ============================================================================
#define AST 72
#define SBUFB (128 * AST * 2)       // bytes per 128-row buffer
#define A_SMEM (4 * SBUFB)          // 73728 bytes: 2 stages x (K128, V128)

__global__ __launch_bounds__(256) void attn_f16(
    const half_t* __restrict__ Qg, const half_t* __restrict__ Kg,
    const half_t* __restrict__ Vg, half_t* __restrict__ Og)
{
    extern __shared__ half_t sa_[];
    const uint32_t sbase = smem_u32(sa_);
    const int tid = threadIdx.x, lane = tid & 31, wq = tid >> 5;
    const int q0 = blockIdx.x * 128, hd = blockIdx.y, bb = blockIdx.z;
    const size_t gbase = ((size_t)bb * T_) * D_ + (size_t)hd * 64;

    // ---- Load Q tile (128 rows), extract fragments ----
    {
        const half_t* qp = Qg + gbase + (size_t)q0 * D_;
#pragma unroll
        for (int it = 0; it < 4; ++it) {
            const int ch = tid + it * 256;
            const int r = ch >> 3, c8 = ch & 7;
            cp16(sbase + (r * AST + c8 * 8) * 2, qp + (size_t)r * D_ + c8 * 8);
        }
        CP_COMMIT(); CP_WAIT0();
        __syncthreads();
    }
    uint32_t qf[4][4];
    {
        const int l15 = lane & 15;
        const int ao = (lane & 16) ? 8 : 0;
#pragma unroll
        for (int ka = 0; ka < 4; ++ka) {
            const uint32_t off = (uint32_t)((wq * 16 + l15) * AST + ka * 16 + ao) * 2;
            ldm4(qf[ka], sbase + off);
        }
    }
    __syncthreads();

    float O[8][4] = {};
    float Ol[4] = {};                 // l accumulator (ones-column mma)
    float m0 = -1e30f, m1 = -1e30f;
    const uint32_t ones_b = (lane < 4) ? 0x3C003C00u : 0u;  // B frag: col 0 = 1.0

    auto issue_kv = [&](int s, int t) {   // t = 128-row stage index (0..15)
        const half_t* srcs[2] = {Kg, Vg};
#pragma unroll
        for (int bi = 0; bi < 2; ++bi) {
            const half_t* g0 = srcs[bi] + gbase + (size_t)(t * 128) * D_;
#pragma unroll
            for (int it = 0; it < 4; ++it) {
                const int ch = tid + it * 256;
                const int r = ch >> 3, c8 = ch & 7;
                cp16(sbase + (s * 2 + bi) * SBUFB + (r * AST + c8 * 8) * 2,
                     g0 + (size_t)r * D_ + c8 * 8);
            }
        }
        CP_COMMIT();
    };

    issue_kv(0, 0);
    for (int t = 0; t < 16; ++t) {
        CP_WAIT0();
        __syncthreads();
        if (t + 1 < 16) issue_kv((t + 1) & 1, t + 1);
        const uint32_t kTile = sbase + (uint32_t)((t & 1) * 2) * SBUFB;
        const uint32_t vTile = kTile + SBUFB;

#pragma unroll
        for (int sub = 0; sub < 2; ++sub) {
            const int rofs = sub * 64;

            // ---- S = Q K^T (log2-domain: Q pre-scaled by 0.125*log2e) ----
            float S[8][4] = {};
            {
                const int l7 = lane & 7;
                const int bro = (lane & 16) ? 8 : 0;
                const int bko = (lane & 8) ? 8 : 0;
#pragma unroll
                for (int ka = 0; ka < 4; ++ka)
#pragma unroll
                    for (int nb = 0; nb < 4; ++nb) {
                        const uint32_t off =
                            (uint32_t)((rofs + nb * 16 + l7 + bro) * AST + ka * 16 + bko) * 2;
                        uint32_t kf[4];
                        ldm4(kf, kTile + off);
                        mma_f16(S[2 * nb],     qf[ka], kf[0], kf[1]);
                        mma_f16(S[2 * nb + 1], qf[ka], kf[2], kf[3]);
                    }
            }

            // ---- Online softmax: p = 2^(S - m), computed straight to f16x2 ----
            float mx0 = -1e30f, mx1 = -1e30f;
#pragma unroll
            for (int j = 0; j < 8; ++j) {
                mx0 = fmaxf(mx0, fmaxf(S[j][0], S[j][1]));
                mx1 = fmaxf(mx1, fmaxf(S[j][2], S[j][3]));
            }
            mx0 = fmaxf(mx0, __shfl_xor_sync(0xffffffffu, mx0, 1));
            mx0 = fmaxf(mx0, __shfl_xor_sync(0xffffffffu, mx0, 2));
            mx1 = fmaxf(mx1, __shfl_xor_sync(0xffffffffu, mx1, 1));
            mx1 = fmaxf(mx1, __shfl_xor_sync(0xffffffffu, mx1, 2));
            const float mn0 = fmaxf(m0, mx0), mn1 = fmaxf(m1, mx1);
            const float c0 = ex2_f(m0 - mn0), c1 = ex2_f(m1 - mn1);
            m0 = mn0; m1 = mn1;

            uint32_t pf[4][4];
#pragma unroll
            for (int j = 0; j < 8; ++j) {
                const int tj = j >> 1, o = (j & 1) * 2;
                pf[tj][o]     = ex2_h2(pkh(S[j][0] - mn0, S[j][1] - mn0));
                pf[tj][o + 1] = ex2_h2(pkh(S[j][2] - mn1, S[j][3] - mn1));
            }
#pragma unroll
            for (int j = 0; j < 8; ++j) {
                O[j][0] *= c0; O[j][1] *= c0; O[j][2] *= c1; O[j][3] *= c1;
            }
            Ol[0] *= c0; Ol[1] *= c0; Ol[2] *= c1; Ol[3] *= c1;

            // ---- O += P V ; l-column += P @ ones ----
            {
                const int l15 = lane & 15;
                const int no = (lane & 16) ? 8 : 0;
#pragma unroll
                for (int kt = 0; kt < 4; ++kt) {
#pragma unroll
                    for (int nb = 0; nb < 4; ++nb) {
                        const uint32_t off =
                            (uint32_t)((rofs + kt * 16 + l15) * AST + nb * 16 + no) * 2;
                        uint32_t vf[4];
                        ldm4t(vf, vTile + off);
                        mma_f16(O[2 * nb],     pf[kt], vf[0], vf[1]);
                        mma_f16(O[2 * nb + 1], pf[kt], vf[2], vf[3]);
                    }
                    mma_f16(Ol, pf[kt], ones_b, ones_b);
                }
            }
        }
    }

    // ---- Epilogue: l from ones-column (lane lc==0), normalize, store ----
    const int lr = lane >> 2, lc = lane & 3;
    const float l0 = __shfl_sync(0xffffffffu, Ol[0], lane & ~3);
    const float l1 = __shfl_sync(0xffffffffu, Ol[2], lane & ~3);
    const float inv0 = 1.f / l0, inv1 = 1.f / l1;
    const size_t rA = (size_t)bb * T_ + q0 + wq * 16 + lr;
    const size_t rB = rA + 8;
#pragma unroll
    for (int j = 0; j < 8; ++j) {
        const int cg = hd * 64 + j * 8 + lc * 2;
        *(uint32_t*)(Og + rA * D_ + cg) = pkh(O[j][0] * inv0, O[j][1] * inv0);
        *(uint32_t*)(Og + rB * D_ + cg) = pkh(O[j][2] * inv1, O[j][3] * inv1);
    }
}

// ============================================================================
extern "C" void kernel_launch(void* const* d_in, const int* in_sizes, int n_in,
                              void* d_out, int out_size)
{
    (void)in_sizes; (void)n_in; (void)out_size;
    const float* q   = (const float*)d_in[0];
    const float* k   = (const float*)d_in[1];
    const float* v   = (const float*)d_in[2];
    const float* Wq  = (const float*)d_in[3];
    const float* b_q = (const float*)d_in[4];
    const float* Wk  = (const float*)d_in[5];
    const float* b_k = (const float*)d_in[6];
    const float* Wv  = (const float*)d_in[7];
    const float* b_v = (const float*)d_in[8];
    const float* Wo  = (const float*)d_in[9];
    const float* b_o = (const float*)d_in[10];
    float* out = (float*)d_out;

    half_t *in3, *qkv, *att, *w4;
    cudaGetSymbolAddress((void**)&in3, g_in3);
    cudaGetSymbolAddress((void**)&qkv, g_qkv);
    cudaGetSymbolAddress((void**)&att, g_att);
    cudaGetSymbolAddress((void**)&w4,  g_w4);

    cudaFuncSetAttribute(gemm_qkv, cudaFuncAttributeMaxDynamicSharedMemorySize, G_SMEM);
    cudaFuncSetAttribute(gemm_out, cudaFuncAttributeMaxDynamicSharedMemorySize, G_SMEM);
    cudaFuncSetAttribute(attn_f16, cudaFuncAttributeMaxDynamicSharedMemorySize, A_SMEM);

    // Prep: weights (4 transposes, one launch) + activations (3 converts, one launch)
    dim3 tgrid(32, 32, 4), tblk(32, 8);
    transpose_cvt4<<<tgrid, tblk>>>(Wq, Wk, Wv, Wo, w4);
    const int n4 = (int)(MD_ / 4);
    dim3 cgrid(n4 / 256, 3);
    tohalf3<<<cgrid, 256>>>((const float4*)q, (const float4*)k, (const float4*)v,
                            (uint2*)in3, n4);

    // Q/K/V projections in one launch
    dim3 ggrid(D_ / 128, M_ / 128, 3);  // 8 x 64 x 3
    gemm_qkv<<<ggrid, 256, G_SMEM>>>(in3, w4, b_q, b_k, b_v, qkv);

    // Attention
    dim3 agrid(T_ / 128, H_, B_);       // 16 x 16 x 4
    attn_f16<<<agrid, 256, A_SMEM>>>(qkv + 0 * MD_, qkv + 1 * MD_, qkv + 2 * MD_, att);

    // Output projection -> fp32
    dim3 ogrid(D_ / 128, M_ / 128);
    gemm_out<<<ogrid, 256, G_SMEM>>>(att, w4 + 3 * DD_, b_o, out);
}